// round 4
// baseline (speedup 1.0000x reference)
#include <cuda_runtime.h>
#include <cuda_bf16.h>

#define DM 1024
#define NH 16
#define HD 64
#define BATCH 4
#define SEQ 2048
#define MR (BATCH*SEQ)

// Scratch (static device globals -- no allocation allowed)
__device__ float g_Q[MR * DM];
__device__ float g_K[MR * DM];
__device__ float g_V[MR * DM];
__device__ float g_C[MR * DM];

// ---------------------------------------------------------------------------
// GEMM: C[M,N] = A[M,K] @ W[K,N] + bias[N]
// 128x128 block tile, K-tile 16, 256 threads, 8x8 microtile per thread
// ---------------------------------------------------------------------------
#define BM 128
#define BN 128
#define BK 16
#define TM 8
#define TN 8

__global__ __launch_bounds__(256)
void gemm_bias(const float* __restrict__ A, const float* __restrict__ W,
               const float* __restrict__ bias, float* __restrict__ C,
               int M, int N, int K)
{
    __shared__ float As[BK][BM];   // A tile stored transposed
    __shared__ float Ws[BK][BN];

    const int tid = threadIdx.x;
    const int br = blockIdx.y, bc = blockIdx.x;
    const int tr = tid >> 4;          // 0..15
    const int tc = tid & 15;          // 0..15
    const int rowA = tid >> 2;        // 0..63
    const int colA = (tid & 3) << 2;  // 0,4,8,12
    const int rowW = tid >> 5;        // 0..7
    const int colW = (tid & 31) << 2; // 0..124

    const float* Ap = A + br * BM * K;
    const float* Wp = W + bc * BN;

    float acc[TM][TN];
#pragma unroll
    for (int i = 0; i < TM; i++)
#pragma unroll
        for (int j = 0; j < TN; j++) acc[i][j] = 0.f;

    for (int k0 = 0; k0 < K; k0 += BK) {
        // load A tile (128 x 16), store transposed
#pragma unroll
        for (int i = 0; i < BM; i += 64) {
            float4 t = *(const float4*)(Ap + (rowA + i) * K + k0 + colA);
            As[colA + 0][rowA + i] = t.x;
            As[colA + 1][rowA + i] = t.y;
            As[colA + 2][rowA + i] = t.z;
            As[colA + 3][rowA + i] = t.w;
        }
        // load W tile (16 x 128)
#pragma unroll
        for (int i = 0; i < BK; i += 8) {
            *(float4*)(&Ws[rowW + i][colW]) =
                *(const float4*)(Wp + (k0 + rowW + i) * N + colW);
        }
        __syncthreads();

#pragma unroll
        for (int k = 0; k < BK; k++) {
            float ra[TM], rb[TN];
#pragma unroll
            for (int i = 0; i < TM; i += 4) {
                float4 t = *(const float4*)(&As[k][tr * TM + i]);
                ra[i + 0] = t.x; ra[i + 1] = t.y; ra[i + 2] = t.z; ra[i + 3] = t.w;
            }
#pragma unroll
            for (int j = 0; j < TN; j += 4) {
                float4 t = *(const float4*)(&Ws[k][tc * TN + j]);
                rb[j + 0] = t.x; rb[j + 1] = t.y; rb[j + 2] = t.z; rb[j + 3] = t.w;
            }
#pragma unroll
            for (int i = 0; i < TM; i++)
#pragma unroll
                for (int j = 0; j < TN; j++) acc[i][j] += ra[i] * rb[j];
        }
        __syncthreads();
    }

    // epilogue: bias add + vectorized store
#pragma unroll
    for (int i = 0; i < TM; i++) {
        const int row = br * BM + tr * TM + i;
#pragma unroll
        for (int j = 0; j < TN; j += 4) {
            const int col = bc * BN + tc * TN + j;
            float4 bv = *(const float4*)(bias + col);
            float4 r;
            r.x = acc[i][j + 0] + bv.x;
            r.y = acc[i][j + 1] + bv.y;
            r.z = acc[i][j + 2] + bv.z;
            r.w = acc[i][j + 3] + bv.w;
            *(float4*)(C + (size_t)row * N + col) = r;
        }
    }
}

// ---------------------------------------------------------------------------
// Causal flash attention, fp32.
// Block = 128 threads = 128 query rows (one row per thread), one (b,h) per
// blockIdx.y. Keys processed in tiles of 64 (SMEM), online softmax.
// q-row and output accumulator live in registers.
// ---------------------------------------------------------------------------
#define AT_BQ 128
#define AT_BK 64
#define ATTN_SMEM ((AT_BK*HD + AT_BK*HD + AT_BQ*65) * 4)

__global__ __launch_bounds__(AT_BQ)
void attn_kernel(const float* __restrict__ Q, const float* __restrict__ K,
                 const float* __restrict__ V, float* __restrict__ O)
{
    extern __shared__ float sm[];
    float* Ks = sm;                        // 64*64
    float* Vs = sm + AT_BK * HD;           // 64*64
    float* Ss = sm + 2 * AT_BK * HD;       // 128*65 (padded rows)

    const int tid = threadIdx.x;
    const int qb = blockIdx.x;
    const int b = blockIdx.y >> 4;
    const int h = blockIdx.y & 15;
    const int qrow = qb * AT_BQ + tid;

    const float scale = 0.125f;  // 1/sqrt(64)
    const float* qp = Q + (size_t)(b * SEQ + qrow) * DM + h * HD;

    float q[HD], o[HD];
#pragma unroll
    for (int d4 = 0; d4 < HD / 4; d4++) {
        float4 t = ((const float4*)qp)[d4];
        q[d4 * 4 + 0] = t.x * scale;
        q[d4 * 4 + 1] = t.y * scale;
        q[d4 * 4 + 2] = t.z * scale;
        q[d4 * 4 + 3] = t.w * scale;
        o[d4 * 4 + 0] = 0.f; o[d4 * 4 + 1] = 0.f;
        o[d4 * 4 + 2] = 0.f; o[d4 * 4 + 3] = 0.f;
    }
    float m = -1e30f, l = 0.f;

    const int ntiles = 2 * (qb + 1);  // causal: keys <= (qb+1)*128-1
    const float* Kbh = K + (size_t)b * SEQ * DM + h * HD;
    const float* Vbh = V + (size_t)b * SEQ * DM + h * HD;

    for (int kt = 0; kt < ntiles; kt++) {
        // cooperative load of K/V tiles: 64 rows x 64 cols, float4 granules
#pragma unroll
        for (int it = 0; it < 8; it++) {
            const int idx = it * AT_BQ + tid;       // 0..1023
            const int j = idx >> 4;                 // key row in tile
            const int d4 = idx & 15;                // float4 within row
            const size_t goff = (size_t)(kt * AT_BK + j) * DM;
            ((float4*)Ks)[idx] = *((const float4*)(Kbh + goff) + d4);
            ((float4*)Vs)[idx] = *((const float4*)(Vbh + goff) + d4);
        }
        __syncthreads();

        // scores for my row vs 64 keys
        float mnew = m;
        float* srow = Ss + tid * 65;
#pragma unroll 4
        for (int j = 0; j < AT_BK; j++) {
            const float4* kr = (const float4*)(Ks + j * HD);
            float s = 0.f;
#pragma unroll
            for (int d4 = 0; d4 < HD / 4; d4++) {
                float4 kv = kr[d4];
                s += q[d4 * 4 + 0] * kv.x + q[d4 * 4 + 1] * kv.y
                   + q[d4 * 4 + 2] * kv.z + q[d4 * 4 + 3] * kv.w;
            }
            if (kt * AT_BK + j > qrow) s = -1e30f;  // causal mask
            srow[j] = s;
            mnew = fmaxf(mnew, s);
        }

        const float corr = __expf(m - mnew);
        m = mnew;
        l *= corr;
#pragma unroll
        for (int d = 0; d < HD; d++) o[d] *= corr;

#pragma unroll 2
        for (int j = 0; j < AT_BK; j++) {
            const float p = __expf(srow[j] - m);
            l += p;
            const float4* vr = (const float4*)(Vs + j * HD);
#pragma unroll
            for (int d4 = 0; d4 < HD / 4; d4++) {
                float4 vv = vr[d4];
                o[d4 * 4 + 0] += p * vv.x;
                o[d4 * 4 + 1] += p * vv.y;
                o[d4 * 4 + 2] += p * vv.z;
                o[d4 * 4 + 3] += p * vv.w;
            }
        }
        __syncthreads();
    }

    const float inv = 1.f / l;
    float* op = O + (size_t)(b * SEQ + qrow) * DM + h * HD;
#pragma unroll
    for (int d4 = 0; d4 < HD / 4; d4++) {
        float4 r;
        r.x = o[d4 * 4 + 0] * inv;
        r.y = o[d4 * 4 + 1] * inv;
        r.z = o[d4 * 4 + 2] * inv;
        r.w = o[d4 * 4 + 3] * inv;
        ((float4*)op)[d4] = r;
    }
}

// ---------------------------------------------------------------------------
// kernel_launch
// ---------------------------------------------------------------------------
extern "C" void kernel_launch(void* const* d_in, const int* in_sizes, int n_in,
                              void* d_out, int out_size)
{
    const float* xq = (const float*)d_in[0];
    const float* xk = (const float*)d_in[1];
    const float* xv = (const float*)d_in[2];
    const float* Wq = (const float*)d_in[3];
    const float* bq = (const float*)d_in[4];
    const float* Wk = (const float*)d_in[5];
    const float* bk = (const float*)d_in[6];
    const float* Wv = (const float*)d_in[7];
    const float* bv = (const float*)d_in[8];
    const float* Wo = (const float*)d_in[9];
    const float* bo = (const float*)d_in[10];
    float* out = (float*)d_out;

    float *Qp, *Kp, *Vp, *Cp;
    cudaGetSymbolAddress((void**)&Qp, g_Q);
    cudaGetSymbolAddress((void**)&Kp, g_K);
    cudaGetSymbolAddress((void**)&Vp, g_V);
    cudaGetSymbolAddress((void**)&Cp, g_C);

    const dim3 gg(DM / BN, MR / BM);

    gemm_bias<<<gg, 256>>>(xq, Wq, bq, Qp, MR, DM, DM);
    gemm_bias<<<gg, 256>>>(xk, Wk, bk, Kp, MR, DM, DM);
    gemm_bias<<<gg, 256>>>(xv, Wv, bv, Vp, MR, DM, DM);

    cudaFuncSetAttribute(attn_kernel,
                         cudaFuncAttributeMaxDynamicSharedMemorySize, ATTN_SMEM);
    attn_kernel<<<dim3(SEQ / AT_BQ, BATCH * NH), AT_BQ, ATTN_SMEM>>>(Qp, Kp, Vp, Cp);

    gemm_bias<<<gg, 256>>>(Cp, Wo, bo, out, MR, DM, DM);
}

// round 8
// speedup vs baseline: 1.6053x; 1.6053x over previous
#include <cuda_runtime.h>
#include <cuda_bf16.h>
#include <cstdint>

#define DM 1024
#define NH 16
#define HD 64
#define BATCH 4
#define SEQ 2048
#define MR (BATCH*SEQ)

// ---------------------------------------------------------------------------
// Scratch (static device globals -- no allocation allowed)
// ---------------------------------------------------------------------------
__device__ float g_Q[MR * DM];
__device__ float g_K[MR * DM];
__device__ float g_V[MR * DM];
__device__ float g_C[MR * DM];

// ---------------------------------------------------------------------------
// Helpers
// ---------------------------------------------------------------------------
__device__ __forceinline__ uint32_t smem_u32(const void* p) {
    uint32_t a;
    asm("{ .reg .u64 t; cvta.to.shared.u64 t, %1; cvt.u32.u64 %0, t; }"
        : "=r"(a) : "l"(p));
    return a;
}
__device__ __forceinline__ void cp16(uint32_t dst, const void* src) {
    asm volatile("cp.async.cg.shared.global [%0], [%1], 16;" :: "r"(dst), "l"(src));
}
__device__ __forceinline__ void cp_commit() {
    asm volatile("cp.async.commit_group;" ::: "memory");
}
template <int N>
__device__ __forceinline__ void cp_wait() {
    asm volatile("cp.async.wait_group %0;" :: "n"(N) : "memory");
}
__device__ __forceinline__ uint32_t f2tf32(float x) {
    uint32_t u;
    asm("cvt.rna.tf32.f32 %0, %1;" : "=r"(u) : "f"(x));
    return u;
}
__device__ __forceinline__ void mma_tf32(float* c, const uint32_t* a, const uint32_t* b) {
    asm volatile(
        "mma.sync.aligned.m16n8k8.row.col.f32.tf32.tf32.f32 "
        "{%0,%1,%2,%3}, {%4,%5,%6,%7}, {%8,%9}, {%0,%1,%2,%3};"
        : "+f"(c[0]), "+f"(c[1]), "+f"(c[2]), "+f"(c[3])
        : "r"(a[0]), "r"(a[1]), "r"(a[2]), "r"(a[3]), "r"(b[0]), "r"(b[1]));
}

// ---------------------------------------------------------------------------
// tf32 tensor-core GEMM: C[M=8192, N=1024] = A[M,K=1024] @ W[K,N] + bias
// CTA tile 128x128, BK=32, 256 threads, warp grid 2(m) x 4(n), warp tile 64x32.
// Double-buffered cp.async. Fragments converted to tf32 (rna) at load.
// ---------------------------------------------------------------------------
#define GBM 128
#define GBN 128
#define GBK 32
#define ASTR 36           // A smem row stride (floats): conflict-free, 16B-aligned
#define WSTR 136          // W smem row stride (floats): conflict-free, 16B-aligned
#define ASZF (GBM * ASTR) // 4608 floats
#define WSZF (GBK * WSTR) // 4352 floats
#define STAGEF (ASZF + WSZF)            // 8960 floats per stage
#define GSMEM (2 * STAGEF * 4)          // 71680 bytes
#define GNITER (DM / GBK)               // 32

__global__ __launch_bounds__(256, 2)
void gemm_mma(const float* __restrict__ A, const float* __restrict__ W,
              const float* __restrict__ bias, float* __restrict__ C)
{
    extern __shared__ float sh[];
    const uint32_t smb = smem_u32(sh);

    const int tid = threadIdx.x;
    const int wid = tid >> 5;
    const int lane = tid & 31;
    const int tr = lane >> 2;      // groupID 0..7
    const int tk = lane & 3;       // threadID-in-group 0..3
    const int warp_m = wid >> 2;   // 0..1
    const int warp_n = wid & 3;    // 0..3
    const int br = blockIdx.y, bc = blockIdx.x;

    const float* Ab = A + (size_t)br * GBM * DM;
    const float* Wb = W + bc * GBN;

    float acc[4][4][4];
#pragma unroll
    for (int mt = 0; mt < 4; mt++)
#pragma unroll
        for (int nt = 0; nt < 4; nt++)
#pragma unroll
            for (int c = 0; c < 4; c++) acc[mt][nt][c] = 0.f;

    // ---- stage loader: A tile 128x32, W tile 32x128 (k-major, straight) ----
    auto load_stage = [&](int s, int k0) {
        const uint32_t aB = smb + (uint32_t)(s * STAGEF) * 4;
        const uint32_t wB = aB + ASZF * 4;
#pragma unroll
        for (int j = 0; j < 4; j++) {
            const int idx = j * 256 + tid;        // 0..1023
            const int rowA = idx >> 3;            // 0..127
            const int cA = idx & 7;               // float4 slot
            cp16(aB + (uint32_t)(rowA * ASTR + cA * 4) * 4,
                 Ab + (size_t)rowA * DM + k0 + cA * 4);
        }
#pragma unroll
        for (int j = 0; j < 4; j++) {
            const int idx = j * 256 + tid;
            const int rowW = idx >> 5;            // 0..31
            const int cW = idx & 31;              // float4 slot
            cp16(wB + (uint32_t)(rowW * WSTR + cW * 4) * 4,
                 Wb + (size_t)(k0 + rowW) * DM + cW * 4);
        }
        cp_commit();
    };

    load_stage(0, 0);

    for (int i = 0; i < GNITER; i++) {
        if (i + 1 < GNITER) {
            load_stage((i + 1) & 1, (i + 1) * GBK);
            cp_wait<1>();
        } else {
            cp_wait<0>();
        }
        __syncthreads();

        const float* as = sh + (i & 1) * STAGEF;
        const float* ws = as + ASZF;

#pragma unroll
        for (int ks = 0; ks < 4; ks++) {
            const int k = ks * 8;
            uint32_t af[4][4], bf[4][2];
#pragma unroll
            for (int mt = 0; mt < 4; mt++) {
                const int row0 = warp_m * 64 + mt * 16 + tr;
                af[mt][0] = f2tf32(as[row0 * ASTR + k + tk]);
                af[mt][1] = f2tf32(as[(row0 + 8) * ASTR + k + tk]);
                af[mt][2] = f2tf32(as[row0 * ASTR + k + tk + 4]);
                af[mt][3] = f2tf32(as[(row0 + 8) * ASTR + k + tk + 4]);
            }
#pragma unroll
            for (int nt = 0; nt < 4; nt++) {
                const int col = warp_n * 32 + nt * 8 + tr;
                bf[nt][0] = f2tf32(ws[(k + tk) * WSTR + col]);
                bf[nt][1] = f2tf32(ws[(k + tk + 4) * WSTR + col]);
            }
#pragma unroll
            for (int mt = 0; mt < 4; mt++)
#pragma unroll
                for (int nt = 0; nt < 4; nt++)
                    mma_tf32(acc[mt][nt], af[mt], bf[nt]);
        }
        __syncthreads();
    }

    // ---- epilogue: bias add, float2 stores ----
#pragma unroll
    for (int mt = 0; mt < 4; mt++) {
        const int row = br * GBM + warp_m * 64 + mt * 16 + tr;
#pragma unroll
        for (int nt = 0; nt < 4; nt++) {
            const int col = bc * GBN + warp_n * 32 + nt * 8 + 2 * tk;
            const float2 bv = *(const float2*)(bias + col);
            float2 r0, r1;
            r0.x = acc[mt][nt][0] + bv.x;
            r0.y = acc[mt][nt][1] + bv.y;
            r1.x = acc[mt][nt][2] + bv.x;
            r1.y = acc[mt][nt][3] + bv.y;
            *(float2*)(C + (size_t)row * DM + col) = r0;
            *(float2*)(C + (size_t)(row + 8) * DM + col) = r1;
        }
    }
}

// ---------------------------------------------------------------------------
// Causal flash attention, fp32 (unchanged from passing R3 kernel)
// ---------------------------------------------------------------------------
#define AT_BQ 128
#define AT_BK 64
#define ATTN_SMEM ((AT_BK*HD + AT_BK*HD + AT_BQ*65) * 4)

__global__ __launch_bounds__(AT_BQ)
void attn_kernel(const float* __restrict__ Q, const float* __restrict__ K,
                 const float* __restrict__ V, float* __restrict__ O)
{
    extern __shared__ float smf[];
    float* Ks = smf;
    float* Vs = smf + AT_BK * HD;
    float* Ss = smf + 2 * AT_BK * HD;

    const int tid = threadIdx.x;
    const int qb = blockIdx.x;
    const int b = blockIdx.y >> 4;
    const int h = blockIdx.y & 15;
    const int qrow = qb * AT_BQ + tid;

    const float scale = 0.125f;
    const float* qp = Q + (size_t)(b * SEQ + qrow) * DM + h * HD;

    float q[HD], o[HD];
#pragma unroll
    for (int d4 = 0; d4 < HD / 4; d4++) {
        float4 t = ((const float4*)qp)[d4];
        q[d4 * 4 + 0] = t.x * scale;
        q[d4 * 4 + 1] = t.y * scale;
        q[d4 * 4 + 2] = t.z * scale;
        q[d4 * 4 + 3] = t.w * scale;
        o[d4 * 4 + 0] = 0.f; o[d4 * 4 + 1] = 0.f;
        o[d4 * 4 + 2] = 0.f; o[d4 * 4 + 3] = 0.f;
    }
    float m = -1e30f, l = 0.f;

    const int ntiles = 2 * (qb + 1);
    const float* Kbh = K + (size_t)b * SEQ * DM + h * HD;
    const float* Vbh = V + (size_t)b * SEQ * DM + h * HD;

    for (int kt = 0; kt < ntiles; kt++) {
#pragma unroll
        for (int it = 0; it < 8; it++) {
            const int idx = it * AT_BQ + tid;
            const int j = idx >> 4;
            const int d4 = idx & 15;
            const size_t goff = (size_t)(kt * AT_BK + j) * DM;
            ((float4*)Ks)[idx] = *((const float4*)(Kbh + goff) + d4);
            ((float4*)Vs)[idx] = *((const float4*)(Vbh + goff) + d4);
        }
        __syncthreads();

        float mnew = m;
        float* srow = Ss + tid * 65;
#pragma unroll 4
        for (int j = 0; j < AT_BK; j++) {
            const float4* kr = (const float4*)(Ks + j * HD);
            float s = 0.f;
#pragma unroll
            for (int d4 = 0; d4 < HD / 4; d4++) {
                float4 kv = kr[d4];
                s += q[d4 * 4 + 0] * kv.x + q[d4 * 4 + 1] * kv.y
                   + q[d4 * 4 + 2] * kv.z + q[d4 * 4 + 3] * kv.w;
            }
            if (kt * AT_BK + j > qrow) s = -1e30f;
            srow[j] = s;
            mnew = fmaxf(mnew, s);
        }

        const float corr = __expf(m - mnew);
        m = mnew;
        l *= corr;
#pragma unroll
        for (int d = 0; d < HD; d++) o[d] *= corr;

#pragma unroll 2
        for (int j = 0; j < AT_BK; j++) {
            const float p = __expf(srow[j] - m);
            l += p;
            const float4* vr = (const float4*)(Vs + j * HD);
#pragma unroll
            for (int d4 = 0; d4 < HD / 4; d4++) {
                float4 vv = vr[d4];
                o[d4 * 4 + 0] += p * vv.x;
                o[d4 * 4 + 1] += p * vv.y;
                o[d4 * 4 + 2] += p * vv.z;
                o[d4 * 4 + 3] += p * vv.w;
            }
        }
        __syncthreads();
    }

    const float inv = 1.f / l;
    float* op = O + (size_t)(b * SEQ + qrow) * DM + h * HD;
#pragma unroll
    for (int d4 = 0; d4 < HD / 4; d4++) {
        float4 r;
        r.x = o[d4 * 4 + 0] * inv;
        r.y = o[d4 * 4 + 1] * inv;
        r.z = o[d4 * 4 + 2] * inv;
        r.w = o[d4 * 4 + 3] * inv;
        ((float4*)op)[d4] = r;
    }
}

// ---------------------------------------------------------------------------
// kernel_launch
// ---------------------------------------------------------------------------
extern "C" void kernel_launch(void* const* d_in, const int* in_sizes, int n_in,
                              void* d_out, int out_size)
{
    const float* xq = (const float*)d_in[0];
    const float* xk = (const float*)d_in[1];
    const float* xv = (const float*)d_in[2];
    const float* Wq = (const float*)d_in[3];
    const float* bq = (const float*)d_in[4];
    const float* Wk = (const float*)d_in[5];
    const float* bk = (const float*)d_in[6];
    const float* Wv = (const float*)d_in[7];
    const float* bv = (const float*)d_in[8];
    const float* Wo = (const float*)d_in[9];
    const float* bo = (const float*)d_in[10];
    float* out = (float*)d_out;

    float *Qp, *Kp, *Vp, *Cp;
    cudaGetSymbolAddress((void**)&Qp, g_Q);
    cudaGetSymbolAddress((void**)&Kp, g_K);
    cudaGetSymbolAddress((void**)&Vp, g_V);
    cudaGetSymbolAddress((void**)&Cp, g_C);

    cudaFuncSetAttribute(gemm_mma, cudaFuncAttributeMaxDynamicSharedMemorySize, GSMEM);
    cudaFuncSetAttribute(attn_kernel, cudaFuncAttributeMaxDynamicSharedMemorySize,
                         ATTN_SMEM);

    const dim3 gg(DM / GBN, MR / GBM);   // (8, 64)

    gemm_mma<<<gg, 256, GSMEM>>>(xq, Wq, bq, Qp);
    gemm_mma<<<gg, 256, GSMEM>>>(xk, Wk, bk, Kp);
    gemm_mma<<<gg, 256, GSMEM>>>(xv, Wv, bv, Vp);

    attn_kernel<<<dim3(SEQ / AT_BQ, BATCH * NH), AT_BQ, ATTN_SMEM>>>(Qp, Kp, Vp, Cp);

    gemm_mma<<<gg, 256, GSMEM>>>(Cp, Wo, bo, out);
}

// round 10
// speedup vs baseline: 3.5954x; 2.2397x over previous
#include <cuda_runtime.h>
#include <cuda_bf16.h>
#include <cstdint>

#define DM 1024
#define NH 16
#define HD 64
#define BATCH 4
#define SEQ 2048
#define MR (BATCH*SEQ)

// ---------------------------------------------------------------------------
// Scratch (static device globals -- no allocation allowed)
// ---------------------------------------------------------------------------
__device__ float g_Q[MR * DM];
__device__ float g_K[MR * DM];
__device__ float g_V[MR * DM];
__device__ float g_C[MR * DM];

// ---------------------------------------------------------------------------
// Helpers
// ---------------------------------------------------------------------------
__device__ __forceinline__ uint32_t smem_u32(const void* p) {
    uint32_t a;
    asm("{ .reg .u64 t; cvta.to.shared.u64 t, %1; cvt.u32.u64 %0, t; }"
        : "=r"(a) : "l"(p));
    return a;
}
__device__ __forceinline__ void cp16(uint32_t dst, const void* src) {
    asm volatile("cp.async.cg.shared.global [%0], [%1], 16;" :: "r"(dst), "l"(src));
}
__device__ __forceinline__ void cp_commit() {
    asm volatile("cp.async.commit_group;" ::: "memory");
}
template <int N>
__device__ __forceinline__ void cp_wait() {
    asm volatile("cp.async.wait_group %0;" :: "n"(N) : "memory");
}
__device__ __forceinline__ uint32_t f2tf32(float x) {
    uint32_t u;
    asm("cvt.rna.tf32.f32 %0, %1;" : "=r"(u) : "f"(x));
    return u;
}
__device__ __forceinline__ float ex2(float x) {
    float y;
    asm("ex2.approx.ftz.f32 %0, %1;" : "=f"(y) : "f"(x));
    return y;
}
__device__ __forceinline__ void mma_tf32(float* c, const uint32_t* a, const uint32_t* b) {
    asm volatile(
        "mma.sync.aligned.m16n8k8.row.col.f32.tf32.tf32.f32 "
        "{%0,%1,%2,%3}, {%4,%5,%6,%7}, {%8,%9}, {%0,%1,%2,%3};"
        : "+f"(c[0]), "+f"(c[1]), "+f"(c[2]), "+f"(c[3])
        : "r"(a[0]), "r"(a[1]), "r"(a[2]), "r"(a[3]), "r"(b[0]), "r"(b[1]));
}

// ---------------------------------------------------------------------------
// tf32 tensor-core GEMM: C[M=8192, N=1024] = A[M,K=1024] @ W[K,N] + bias
// (unchanged from R7 passing kernel)
// ---------------------------------------------------------------------------
#define GBM 128
#define GBN 128
#define GBK 32
#define ASTR 36
#define WSTR 136
#define ASZF (GBM * ASTR)
#define WSZF (GBK * WSTR)
#define STAGEF (ASZF + WSZF)
#define GSMEM (2 * STAGEF * 4)
#define GNITER (DM / GBK)

__global__ __launch_bounds__(256, 2)
void gemm_mma(const float* __restrict__ A, const float* __restrict__ W,
              const float* __restrict__ bias, float* __restrict__ C)
{
    extern __shared__ float sh[];
    const uint32_t smb = smem_u32(sh);

    const int tid = threadIdx.x;
    const int wid = tid >> 5;
    const int lane = tid & 31;
    const int tr = lane >> 2;
    const int tk = lane & 3;
    const int warp_m = wid >> 2;
    const int warp_n = wid & 3;
    const int br = blockIdx.y, bc = blockIdx.x;

    const float* Ab = A + (size_t)br * GBM * DM;
    const float* Wb = W + bc * GBN;

    float acc[4][4][4];
#pragma unroll
    for (int mt = 0; mt < 4; mt++)
#pragma unroll
        for (int nt = 0; nt < 4; nt++)
#pragma unroll
            for (int c = 0; c < 4; c++) acc[mt][nt][c] = 0.f;

    auto load_stage = [&](int s, int k0) {
        const uint32_t aB = smb + (uint32_t)(s * STAGEF) * 4;
        const uint32_t wB = aB + ASZF * 4;
#pragma unroll
        for (int j = 0; j < 4; j++) {
            const int idx = j * 256 + tid;
            const int rowA = idx >> 3;
            const int cA = idx & 7;
            cp16(aB + (uint32_t)(rowA * ASTR + cA * 4) * 4,
                 Ab + (size_t)rowA * DM + k0 + cA * 4);
        }
#pragma unroll
        for (int j = 0; j < 4; j++) {
            const int idx = j * 256 + tid;
            const int rowW = idx >> 5;
            const int cW = idx & 31;
            cp16(wB + (uint32_t)(rowW * WSTR + cW * 4) * 4,
                 Wb + (size_t)(k0 + rowW) * DM + cW * 4);
        }
        cp_commit();
    };

    load_stage(0, 0);

    for (int i = 0; i < GNITER; i++) {
        if (i + 1 < GNITER) {
            load_stage((i + 1) & 1, (i + 1) * GBK);
            cp_wait<1>();
        } else {
            cp_wait<0>();
        }
        __syncthreads();

        const float* as = sh + (i & 1) * STAGEF;
        const float* ws = as + ASZF;

#pragma unroll
        for (int ks = 0; ks < 4; ks++) {
            const int k = ks * 8;
            uint32_t af[4][4], bf[4][2];
#pragma unroll
            for (int mt = 0; mt < 4; mt++) {
                const int row0 = warp_m * 64 + mt * 16 + tr;
                af[mt][0] = f2tf32(as[row0 * ASTR + k + tk]);
                af[mt][1] = f2tf32(as[(row0 + 8) * ASTR + k + tk]);
                af[mt][2] = f2tf32(as[row0 * ASTR + k + tk + 4]);
                af[mt][3] = f2tf32(as[(row0 + 8) * ASTR + k + tk + 4]);
            }
#pragma unroll
            for (int nt = 0; nt < 4; nt++) {
                const int col = warp_n * 32 + nt * 8 + tr;
                bf[nt][0] = f2tf32(ws[(k + tk) * WSTR + col]);
                bf[nt][1] = f2tf32(ws[(k + tk + 4) * WSTR + col]);
            }
#pragma unroll
            for (int mt = 0; mt < 4; mt++)
#pragma unroll
                for (int nt = 0; nt < 4; nt++)
                    mma_tf32(acc[mt][nt], af[mt], bf[nt]);
        }
        __syncthreads();
    }

#pragma unroll
    for (int mt = 0; mt < 4; mt++) {
        const int row = br * GBM + warp_m * 64 + mt * 16 + tr;
#pragma unroll
        for (int nt = 0; nt < 4; nt++) {
            const int col = bc * GBN + warp_n * 32 + nt * 8 + 2 * tk;
            const float2 bv = *(const float2*)(bias + col);
            float2 r0, r1;
            r0.x = acc[mt][nt][0] + bv.x;
            r0.y = acc[mt][nt][1] + bv.y;
            r1.x = acc[mt][nt][2] + bv.x;
            r1.y = acc[mt][nt][3] + bv.y;
            *(float2*)(C + (size_t)row * DM + col) = r0;
            *(float2*)(C + (size_t)(row + 8) * DM + col) = r1;
        }
    }
}

// ---------------------------------------------------------------------------
// Tensor-core causal flash attention (tf32 mma, fp32 softmax)
// 8 warps x 16 q-rows = 128 q per block; 64-key tiles; one (b,h) per block.y
// ---------------------------------------------------------------------------
#define BQ 128
#define KSTR 68                 // K smem row stride (floats) -> QK B-frag conflict-free
#define VSTR 72                 // V smem row stride -> PV B-frag conflict-free
#define PSTR 68                 // P staging row stride -> A-frag conflict-free
#define KS_OFF 0
#define VS_OFF (64 * KSTR)                  // 4352
#define PS_OFF (VS_OFF + 64 * VSTR)         // 8960
#define ATTN2_SMEM ((PS_OFF + 8 * 16 * PSTR) * 4)   // 70656 bytes

__global__ __launch_bounds__(256, 2)
void attn_mma(const float* __restrict__ Q, const float* __restrict__ K,
              const float* __restrict__ V, float* __restrict__ O)
{
    extern __shared__ float smf[];
    float* Ks = smf + KS_OFF;
    float* Vs = smf + VS_OFF;

    const int tid = threadIdx.x;
    const int wid = tid >> 5;
    const int lane = tid & 31;
    const int tr = lane >> 2;        // groupID 0..7
    const int tk = lane & 3;         // thread-in-group 0..3
    const int qb = (SEQ / BQ - 1) - blockIdx.x;   // heavy blocks first
    const int b = blockIdx.y >> 4;
    const int h = blockIdx.y & 15;
    float* Pw = smf + PS_OFF + wid * 16 * PSTR;

    const int r0 = qb * BQ + wid * 16 + tr;   // global q rows owned by thread
    const int r1 = r0 + 8;

    // Q fragments, pre-scaled by 1/sqrt(hd) * log2(e), tf32-rounded
    const float qscale = 0.125f * 1.4426950408889634f;
    const float* Qbh = Q + (size_t)b * SEQ * DM + h * HD;
    uint32_t qf[8][4];
#pragma unroll
    for (int kc = 0; kc < 8; kc++) {
        qf[kc][0] = f2tf32(Qbh[(size_t)r0 * DM + kc * 8 + tk] * qscale);
        qf[kc][1] = f2tf32(Qbh[(size_t)r1 * DM + kc * 8 + tk] * qscale);
        qf[kc][2] = f2tf32(Qbh[(size_t)r0 * DM + kc * 8 + tk + 4] * qscale);
        qf[kc][3] = f2tf32(Qbh[(size_t)r1 * DM + kc * 8 + tk + 4] * qscale);
    }

    float oacc[8][4];
#pragma unroll
    for (int nt = 0; nt < 8; nt++)
#pragma unroll
        for (int c = 0; c < 4; c++) oacc[nt][c] = 0.f;
    float m0 = -1e30f, m1 = -1e30f, l0 = 0.f, l1 = 0.f;

    const float* Kbh = K + (size_t)b * SEQ * DM + h * HD;
    const float* Vbh = V + (size_t)b * SEQ * DM + h * HD;
    const int ntiles = 2 * (qb + 1);

    for (int kt = 0; kt < ntiles; kt++) {
        __syncthreads();
        // cooperative K/V tile load: 64 keys x 64 dims each, float4 granules
#pragma unroll
        for (int j = 0; j < 4; j++) {
            const int idx = j * 256 + tid;      // 0..1023
            const int key = idx >> 4;           // 0..63
            const int d4 = idx & 15;            // float4 slot
            const size_t go = (size_t)(kt * 64 + key) * DM + d4 * 4;
            *(float4*)(Ks + key * KSTR + d4 * 4) = *(const float4*)(Kbh + go);
            *(float4*)(Vs + key * VSTR + d4 * 4) = *(const float4*)(Vbh + go);
        }
        __syncthreads();

        // ---- S = Q @ K^T (tf32 mma) ----
        float sacc[8][4];
#pragma unroll
        for (int nt = 0; nt < 8; nt++)
#pragma unroll
            for (int c = 0; c < 4; c++) sacc[nt][c] = 0.f;

#pragma unroll
        for (int kc = 0; kc < 8; kc++) {
#pragma unroll
            for (int nt = 0; nt < 8; nt++) {
                uint32_t bf[2];
                bf[0] = f2tf32(Ks[(nt * 8 + tr) * KSTR + kc * 8 + tk]);
                bf[1] = f2tf32(Ks[(nt * 8 + tr) * KSTR + kc * 8 + tk + 4]);
                mma_tf32(sacc[nt], qf[kc], bf);
            }
        }

        // ---- causal mask (only the 2 diagonal tiles) ----
        if (kt >= 2 * qb) {
#pragma unroll
            for (int nt = 0; nt < 8; nt++) {
                const int c0 = kt * 64 + nt * 8 + 2 * tk;
                if (c0 > r0)     sacc[nt][0] = -1e30f;
                if (c0 + 1 > r0) sacc[nt][1] = -1e30f;
                if (c0 > r1)     sacc[nt][2] = -1e30f;
                if (c0 + 1 > r1) sacc[nt][3] = -1e30f;
            }
        }

        // ---- online softmax on fragments ----
        float mn0 = m0, mn1 = m1;
#pragma unroll
        for (int nt = 0; nt < 8; nt++) {
            mn0 = fmaxf(mn0, fmaxf(sacc[nt][0], sacc[nt][1]));
            mn1 = fmaxf(mn1, fmaxf(sacc[nt][2], sacc[nt][3]));
        }
        mn0 = fmaxf(mn0, __shfl_xor_sync(0xffffffffu, mn0, 1));
        mn0 = fmaxf(mn0, __shfl_xor_sync(0xffffffffu, mn0, 2));
        mn1 = fmaxf(mn1, __shfl_xor_sync(0xffffffffu, mn1, 1));
        mn1 = fmaxf(mn1, __shfl_xor_sync(0xffffffffu, mn1, 2));

        const float cr0 = ex2(m0 - mn0);
        const float cr1 = ex2(m1 - mn1);
        m0 = mn0; m1 = mn1;
        l0 *= cr0; l1 *= cr1;
#pragma unroll
        for (int nt = 0; nt < 8; nt++) {
            oacc[nt][0] *= cr0; oacc[nt][1] *= cr0;
            oacc[nt][2] *= cr1; oacc[nt][3] *= cr1;
        }

#pragma unroll
        for (int nt = 0; nt < 8; nt++) {
            const float p0 = ex2(sacc[nt][0] - m0);
            const float p1 = ex2(sacc[nt][1] - m0);
            const float p2 = ex2(sacc[nt][2] - m1);
            const float p3 = ex2(sacc[nt][3] - m1);
            l0 += p0 + p1;
            l1 += p2 + p3;
            *(float2*)(Pw + tr * PSTR + nt * 8 + 2 * tk) = make_float2(p0, p1);
            *(float2*)(Pw + (tr + 8) * PSTR + nt * 8 + 2 * tk) = make_float2(p2, p3);
        }
        __syncwarp();

        // ---- O += P @ V (tf32 mma); B-frag reads V[key][d] directly ----
#pragma unroll
        for (int kc = 0; kc < 8; kc++) {
            uint32_t pa[4];
            pa[0] = f2tf32(Pw[tr * PSTR + kc * 8 + tk]);
            pa[1] = f2tf32(Pw[(tr + 8) * PSTR + kc * 8 + tk]);
            pa[2] = f2tf32(Pw[tr * PSTR + kc * 8 + tk + 4]);
            pa[3] = f2tf32(Pw[(tr + 8) * PSTR + kc * 8 + tk + 4]);
#pragma unroll
            for (int nt = 0; nt < 8; nt++) {
                uint32_t bf[2];
                bf[0] = f2tf32(Vs[(kc * 8 + tk) * VSTR + nt * 8 + tr]);
                bf[1] = f2tf32(Vs[(kc * 8 + tk + 4) * VSTR + nt * 8 + tr]);
                mma_tf32(oacc[nt], pa, bf);
            }
        }
        // loop-top __syncthreads orders Pw reads (this tile) vs writes (next)
    }

    // ---- finalize: reduce l across quad, normalize, store ----
    l0 += __shfl_xor_sync(0xffffffffu, l0, 1);
    l0 += __shfl_xor_sync(0xffffffffu, l0, 2);
    l1 += __shfl_xor_sync(0xffffffffu, l1, 1);
    l1 += __shfl_xor_sync(0xffffffffu, l1, 2);
    const float inv0 = 1.f / l0;
    const float inv1 = 1.f / l1;

    float* Ob = O + (size_t)b * SEQ * DM + h * HD;
#pragma unroll
    for (int nt = 0; nt < 8; nt++) {
        const int col = nt * 8 + 2 * tk;
        float2 w0, w1;
        w0.x = oacc[nt][0] * inv0; w0.y = oacc[nt][1] * inv0;
        w1.x = oacc[nt][2] * inv1; w1.y = oacc[nt][3] * inv1;
        *(float2*)(Ob + (size_t)r0 * DM + col) = w0;
        *(float2*)(Ob + (size_t)r1 * DM + col) = w1;
    }
}

// ---------------------------------------------------------------------------
// kernel_launch
// ---------------------------------------------------------------------------
extern "C" void kernel_launch(void* const* d_in, const int* in_sizes, int n_in,
                              void* d_out, int out_size)
{
    const float* xq = (const float*)d_in[0];
    const float* xk = (const float*)d_in[1];
    const float* xv = (const float*)d_in[2];
    const float* Wq = (const float*)d_in[3];
    const float* bq = (const float*)d_in[4];
    const float* Wk = (const float*)d_in[5];
    const float* bk = (const float*)d_in[6];
    const float* Wv = (const float*)d_in[7];
    const float* bv = (const float*)d_in[8];
    const float* Wo = (const float*)d_in[9];
    const float* bo = (const float*)d_in[10];
    float* out = (float*)d_out;

    float *Qp, *Kp, *Vp, *Cp;
    cudaGetSymbolAddress((void**)&Qp, g_Q);
    cudaGetSymbolAddress((void**)&Kp, g_K);
    cudaGetSymbolAddress((void**)&Vp, g_V);
    cudaGetSymbolAddress((void**)&Cp, g_C);

    cudaFuncSetAttribute(gemm_mma, cudaFuncAttributeMaxDynamicSharedMemorySize, GSMEM);
    cudaFuncSetAttribute(attn_mma, cudaFuncAttributeMaxDynamicSharedMemorySize,
                         ATTN2_SMEM);

    const dim3 gg(DM / GBN, MR / GBM);   // (8, 64)

    gemm_mma<<<gg, 256, GSMEM>>>(xq, Wq, bq, Qp);
    gemm_mma<<<gg, 256, GSMEM>>>(xk, Wk, bk, Kp);
    gemm_mma<<<gg, 256, GSMEM>>>(xv, Wv, bv, Vp);

    attn_mma<<<dim3(SEQ / BQ, BATCH * NH), 256, ATTN2_SMEM>>>(Qp, Kp, Vp, Cp);

    gemm_mma<<<gg, 256, GSMEM>>>(Cp, Wo, bo, out);
}

// round 13
// speedup vs baseline: 6.7071x; 1.8655x over previous
#include <cuda_runtime.h>
#include <cuda_fp16.h>
#include <cstdint>

#define DM 1024
#define NH 16
#define HD 64
#define BATCH 4
#define SEQ 2048
#define MR (BATCH*SEQ)

// ---------------------------------------------------------------------------
// Scratch (static device globals -- no allocation allowed)
// ---------------------------------------------------------------------------
__device__ __half g_Qh[MR * DM];      // Q projection (half)
__device__ __half g_Kh[MR * DM];      // K projection
__device__ __half g_Vh[MR * DM];      // V projection
__device__ __half g_Ch[MR * DM];      // attention context
__device__ __half g_Xq[MR * DM];      // half-converted inputs
__device__ __half g_Xk[MR * DM];
__device__ __half g_Xv[MR * DM];
__device__ __half g_Wt[4][DM * DM];   // transposed half weights Wt[n][k] = W[k][n]

// ---------------------------------------------------------------------------
// Helpers
// ---------------------------------------------------------------------------
__device__ __forceinline__ uint32_t smem_u32(const void* p) {
    uint32_t a;
    asm("{ .reg .u64 t; cvta.to.shared.u64 t, %1; cvt.u32.u64 %0, t; }"
        : "=r"(a) : "l"(p));
    return a;
}
__device__ __forceinline__ void cp16(uint32_t dst, const void* src) {
    asm volatile("cp.async.cg.shared.global [%0], [%1], 16;" :: "r"(dst), "l"(src));
}
__device__ __forceinline__ void cp_commit() {
    asm volatile("cp.async.commit_group;" ::: "memory");
}
template <int N>
__device__ __forceinline__ void cp_wait() {
    asm volatile("cp.async.wait_group %0;" :: "n"(N) : "memory");
}
__device__ __forceinline__ float ex2(float x) {
    float y;
    asm("ex2.approx.ftz.f32 %0, %1;" : "=f"(y) : "f"(x));
    return y;
}
__device__ __forceinline__ void mma_f16(float* c, const uint32_t* a,
                                        uint32_t b0, uint32_t b1) {
    asm volatile(
        "mma.sync.aligned.m16n8k16.row.col.f32.f16.f16.f32 "
        "{%0,%1,%2,%3}, {%4,%5,%6,%7}, {%8,%9}, {%0,%1,%2,%3};"
        : "+f"(c[0]), "+f"(c[1]), "+f"(c[2]), "+f"(c[3])
        : "r"(a[0]), "r"(a[1]), "r"(a[2]), "r"(a[3]), "r"(b0), "r"(b1));
}
__device__ __forceinline__ void ldsm4(uint32_t* d, uint32_t a) {
    asm volatile("ldmatrix.sync.aligned.m8n8.x4.shared.b16 {%0,%1,%2,%3}, [%4];"
                 : "=r"(d[0]), "=r"(d[1]), "=r"(d[2]), "=r"(d[3]) : "r"(a));
}
__device__ __forceinline__ void ldsm4t(uint32_t* d, uint32_t a) {
    asm volatile("ldmatrix.sync.aligned.m8n8.x4.trans.shared.b16 {%0,%1,%2,%3}, [%4];"
                 : "=r"(d[0]), "=r"(d[1]), "=r"(d[2]), "=r"(d[3]) : "r"(a));
}
__device__ __forceinline__ uint32_t h2u(__half2 v) {
    return *reinterpret_cast<uint32_t*>(&v);
}

// ---------------------------------------------------------------------------
// fp32 -> fp16 conversion (8 elements/thread)
// ---------------------------------------------------------------------------
__global__ __launch_bounds__(256)
void conv_h(const float* __restrict__ in, __half* __restrict__ out) {
    const int i = (blockIdx.x * 256 + threadIdx.x) * 8;
    const float4 a = *(const float4*)(in + i);
    const float4 b = *(const float4*)(in + i + 4);
    __half2 h0 = __floats2half2_rn(a.x, a.y);
    __half2 h1 = __floats2half2_rn(a.z, a.w);
    __half2 h2 = __floats2half2_rn(b.x, b.y);
    __half2 h3 = __floats2half2_rn(b.z, b.w);
    uint4 u = make_uint4(h2u(h0), h2u(h1), h2u(h2), h2u(h3));
    *(uint4*)(out + i) = u;
}

// ---------------------------------------------------------------------------
// W[K,N] fp32 -> Wt[N,K] fp16 transpose (1024x1024)
// ---------------------------------------------------------------------------
__global__ __launch_bounds__(256)
void wtrans_h(const float* __restrict__ W, __half* __restrict__ Wt) {
    __shared__ float t[32][33];
    const int bx = blockIdx.x * 32, by = blockIdx.y * 32;
    const int tx = threadIdx.x, ty = threadIdx.y;
#pragma unroll
    for (int i = 0; i < 4; i++)
        t[ty + 8 * i][tx] = W[(size_t)(by + ty + 8 * i) * DM + bx + tx];
    __syncthreads();
#pragma unroll
    for (int i = 0; i < 4; i++)
        Wt[(size_t)(bx + ty + 8 * i) * DM + by + tx] = __float2half_rn(t[tx][ty + 8 * i]);
}

// ---------------------------------------------------------------------------
// fp16 tensor-core GEMM: C[8192,1024] = A[M,K] @ Wt[N,K]^T + bias
// CTA 128x128x32, 256 thr, warp 64x32, m16n8k16, double-buffered cp.async.
// A and Wt are half with K contiguous -> all fragments are single u32 LDS.
// ---------------------------------------------------------------------------
#define ASTRH 40                         // halves per smem row (conflict-free)
#define GSTG  (2 * 128 * ASTRH)          // halves per stage (A + B)
#define GSMEMH (2 * GSTG * 2)            // bytes: 40960
#define GNITER (DM / 32)

template <typename OUT>
__global__ __launch_bounds__(256, 2)
void gemm_h(const __half* __restrict__ A, const __half* __restrict__ Wt,
            const float* __restrict__ bias, OUT* __restrict__ C)
{
    extern __shared__ __half shh[];
    const uint32_t smb = smem_u32(shh);

    const int tid = threadIdx.x;
    const int wid = tid >> 5;
    const int lane = tid & 31;
    const int tr = lane >> 2;
    const int tk = lane & 3;
    const int wm = wid >> 2;
    const int wn = wid & 3;
    const int br = blockIdx.y, bc = blockIdx.x;

    const __half* Ab = A + (size_t)br * 128 * DM;
    const __half* Wb = Wt + (size_t)bc * 128 * DM;

    float acc[4][4][4];
#pragma unroll
    for (int mt = 0; mt < 4; mt++)
#pragma unroll
        for (int nt = 0; nt < 4; nt++)
#pragma unroll
            for (int c = 0; c < 4; c++) acc[mt][nt][c] = 0.f;

    auto load_stage = [&](int s, int k0) {
        const uint32_t aB = smb + (uint32_t)(s * GSTG) * 2;
        const uint32_t wB = aB + 128 * ASTRH * 2;
#pragma unroll
        for (int j = 0; j < 2; j++) {
            const int idx = j * 256 + tid;   // 0..511
            const int row = idx >> 2;        // 0..127
            const int c = idx & 3;           // 8-half chunk
            cp16(aB + (uint32_t)(row * ASTRH + c * 8) * 2,
                 Ab + (size_t)row * DM + k0 + c * 8);
        }
#pragma unroll
        for (int j = 0; j < 2; j++) {
            const int idx = j * 256 + tid;
            const int row = idx >> 2;
            const int c = idx & 3;
            cp16(wB + (uint32_t)(row * ASTRH + c * 8) * 2,
                 Wb + (size_t)row * DM + k0 + c * 8);
        }
        cp_commit();
    };

    load_stage(0, 0);

    for (int i = 0; i < GNITER; i++) {
        if (i + 1 < GNITER) {
            load_stage((i + 1) & 1, (i + 1) * 32);
            cp_wait<1>();
        } else {
            cp_wait<0>();
        }
        __syncthreads();

        const __half* as = shh + (i & 1) * GSTG;
        const __half* ws = as + 128 * ASTRH;

#pragma unroll
        for (int ks = 0; ks < 2; ks++) {
            const int kb = ks * 16 + 2 * tk;
            uint32_t af[4][4], bf[4][2];
#pragma unroll
            for (int mt = 0; mt < 4; mt++) {
                const __half* p = as + (wm * 64 + mt * 16 + tr) * ASTRH + kb;
                af[mt][0] = *(const uint32_t*)p;
                af[mt][1] = *(const uint32_t*)(p + 8 * ASTRH);
                af[mt][2] = *(const uint32_t*)(p + 8);
                af[mt][3] = *(const uint32_t*)(p + 8 * ASTRH + 8);
            }
#pragma unroll
            for (int nt = 0; nt < 4; nt++) {
                const __half* p = ws + (wn * 32 + nt * 8 + tr) * ASTRH + kb;
                bf[nt][0] = *(const uint32_t*)p;
                bf[nt][1] = *(const uint32_t*)(p + 8);
            }
#pragma unroll
            for (int mt = 0; mt < 4; mt++)
#pragma unroll
                for (int nt = 0; nt < 4; nt++)
                    mma_f16(acc[mt][nt], af[mt], bf[nt][0], bf[nt][1]);
        }
        __syncthreads();
    }

    // epilogue: bias in fp32, store fp32 or half2
#pragma unroll
    for (int mt = 0; mt < 4; mt++) {
        const int row = br * 128 + wm * 64 + mt * 16 + tr;
#pragma unroll
        for (int nt = 0; nt < 4; nt++) {
            const int col = bc * 128 + wn * 32 + nt * 8 + 2 * tk;
            const float2 bv = *(const float2*)(bias + col);
            const float v0 = acc[mt][nt][0] + bv.x;
            const float v1 = acc[mt][nt][1] + bv.y;
            const float v2 = acc[mt][nt][2] + bv.x;
            const float v3 = acc[mt][nt][3] + bv.y;
            if constexpr (sizeof(OUT) == 4) {
                *(float2*)((float*)C + (size_t)row * DM + col) = make_float2(v0, v1);
                *(float2*)((float*)C + (size_t)(row + 8) * DM + col) = make_float2(v2, v3);
            } else {
                *(uint32_t*)((__half*)C + (size_t)row * DM + col) =
                    h2u(__floats2half2_rn(v0, v1));
                *(uint32_t*)((__half*)C + (size_t)(row + 8) * DM + col) =
                    h2u(__floats2half2_rn(v2, v3));
            }
        }
    }
}

// ---------------------------------------------------------------------------
// fp16 tensor-core causal flash attention
// 8 warps x 16 q-rows = 128 q / block; 64-key tiles; ldmatrix fragments.
// smem (halves): Ks[64][72], Vs[64][72], P[8 warps][16][72]
// ---------------------------------------------------------------------------
#define KSTRH 72
#define ATTNH_SMEM ((2 * 64 * KSTRH + 8 * 16 * KSTRH) * 2)   // 36864 bytes

__global__ __launch_bounds__(256, 2)
void attn_h(const __half* __restrict__ Q, const __half* __restrict__ K,
            const __half* __restrict__ V, __half* __restrict__ O)
{
    extern __shared__ __half sh2[];
    __half* Ks = sh2;
    __half* Vs = sh2 + 64 * KSTRH;
    const int tid = threadIdx.x;
    const int wid = tid >> 5;
    const int lane = tid & 31;
    const int tr = lane >> 2;
    const int tk = lane & 3;
    const int qb = (SEQ / 128 - 1) - blockIdx.x;    // heavy blocks first
    const int b = blockIdx.y >> 4;
    const int h = blockIdx.y & 15;
    __half* Pw = sh2 + 2 * 64 * KSTRH + wid * 16 * KSTRH;

    const uint32_t Ksb = smem_u32(Ks);
    const uint32_t Vsb = smem_u32(Vs);
    const uint32_t Pwb = smem_u32(Pw);

    // ldmatrix per-thread address bases
    const int r8 = lane & 7;
    const int b3 = (lane >> 3) & 1;
    const int b4 = (lane >> 4) & 1;
    const uint32_t kBase = Ksb + (uint32_t)((b4 * 8 + r8) * KSTRH + b3 * 8) * 2;
    const uint32_t pBase = Pwb + (uint32_t)((r8 + b3 * 8) * KSTRH + b4 * 8) * 2;
    const uint32_t vBase = Vsb + (uint32_t)((r8 + b3 * 8) * KSTRH + b4 * 8) * 2;

    const int r0 = qb * 128 + wid * 16 + tr;
    const int r1 = r0 + 8;

    // Q fragments: scale in fp32, round to half2 (one rounding, exact scale)
    const float qs = 0.125f * 1.4426950408889634f;
    const __half* Qbh = Q + (size_t)b * SEQ * DM + h * HD;
    uint32_t qf[4][4];
#pragma unroll
    for (int kc = 0; kc < 4; kc++) {
        const __half* p0 = Qbh + (size_t)r0 * DM + kc * 16 + 2 * tk;
        const __half* p1 = Qbh + (size_t)r1 * DM + kc * 16 + 2 * tk;
#pragma unroll
        for (int j = 0; j < 4; j++) {
            const __half* p = (j & 1) ? p1 : p0;
            const float2 f = __half22float2(*(const __half2*)(p + (j >> 1) * 8));
            qf[kc][j] = h2u(__floats2half2_rn(f.x * qs, f.y * qs));
        }
    }

    float oacc[8][4];
#pragma unroll
    for (int nt = 0; nt < 8; nt++)
#pragma unroll
        for (int c = 0; c < 4; c++) oacc[nt][c] = 0.f;
    float m0 = -1e30f, m1 = -1e30f, l0 = 0.f, l1 = 0.f;

    const __half* Kbh = K + (size_t)b * SEQ * DM + h * HD;
    const __half* Vbh = V + (size_t)b * SEQ * DM + h * HD;
    const int ntiles = 2 * (qb + 1);

    for (int kt = 0; kt < ntiles; kt++) {
        __syncthreads();
        // cooperative K/V tile load: 64 keys x 64 halves, 16B granules
#pragma unroll
        for (int j = 0; j < 2; j++) {
            const int idx = j * 256 + tid;       // 0..511
            const int key = idx >> 3;            // 0..63
            const int c = idx & 7;               // 8-half chunk
            const size_t go = (size_t)(kt * 64 + key) * DM + c * 8;
            *(float4*)(Ks + key * KSTRH + c * 8) = *(const float4*)(Kbh + go);
            *(float4*)(Vs + key * KSTRH + c * 8) = *(const float4*)(Vbh + go);
        }
        __syncthreads();

        // ---- S = Q @ K^T ----
        float sacc[8][4];
#pragma unroll
        for (int nt = 0; nt < 8; nt++)
#pragma unroll
            for (int c = 0; c < 4; c++) sacc[nt][c] = 0.f;

#pragma unroll
        for (int kc = 0; kc < 4; kc++) {
#pragma unroll
            for (int ntp = 0; ntp < 4; ntp++) {
                uint32_t bm[4];
                ldsm4(bm, kBase + (uint32_t)(ntp * 16 * KSTRH + kc * 16) * 2);
                mma_f16(sacc[2 * ntp], qf[kc], bm[0], bm[1]);
                mma_f16(sacc[2 * ntp + 1], qf[kc], bm[2], bm[3]);
            }
        }

        // ---- causal mask (diagonal tiles only) ----
        if (kt >= 2 * qb) {
#pragma unroll
            for (int nt = 0; nt < 8; nt++) {
                const int c0 = kt * 64 + nt * 8 + 2 * tk;
                if (c0 > r0)     sacc[nt][0] = -1e30f;
                if (c0 + 1 > r0) sacc[nt][1] = -1e30f;
                if (c0 > r1)     sacc[nt][2] = -1e30f;
                if (c0 + 1 > r1) sacc[nt][3] = -1e30f;
            }
        }

        // ---- online softmax ----
        float mn0 = m0, mn1 = m1;
#pragma unroll
        for (int nt = 0; nt < 8; nt++) {
            mn0 = fmaxf(mn0, fmaxf(sacc[nt][0], sacc[nt][1]));
            mn1 = fmaxf(mn1, fmaxf(sacc[nt][2], sacc[nt][3]));
        }
        mn0 = fmaxf(mn0, __shfl_xor_sync(0xffffffffu, mn0, 1));
        mn0 = fmaxf(mn0, __shfl_xor_sync(0xffffffffu, mn0, 2));
        mn1 = fmaxf(mn1, __shfl_xor_sync(0xffffffffu, mn1, 1));
        mn1 = fmaxf(mn1, __shfl_xor_sync(0xffffffffu, mn1, 2));

        const float cr0 = ex2(m0 - mn0);
        const float cr1 = ex2(m1 - mn1);
        m0 = mn0; m1 = mn1;
        l0 *= cr0; l1 *= cr1;
#pragma unroll
        for (int nt = 0; nt < 8; nt++) {
            oacc[nt][0] *= cr0; oacc[nt][1] *= cr0;
            oacc[nt][2] *= cr1; oacc[nt][3] *= cr1;
        }

#pragma unroll
        for (int nt = 0; nt < 8; nt++) {
            const float p0 = ex2(sacc[nt][0] - m0);
            const float p1 = ex2(sacc[nt][1] - m0);
            const float p2 = ex2(sacc[nt][2] - m1);
            const float p3 = ex2(sacc[nt][3] - m1);
            l0 += p0 + p1;
            l1 += p2 + p3;
            *(uint32_t*)(Pw + tr * KSTRH + nt * 8 + 2 * tk) =
                h2u(__floats2half2_rn(p0, p1));
            *(uint32_t*)(Pw + (tr + 8) * KSTRH + nt * 8 + 2 * tk) =
                h2u(__floats2half2_rn(p2, p3));
        }
        __syncwarp();

        // ---- O += P @ V (B-frags via ldmatrix.trans on V[key][dim]) ----
#pragma unroll
        for (int kc = 0; kc < 4; kc++) {
            uint32_t pa[4];
            ldsm4(pa, pBase + (uint32_t)(kc * 16) * 2);
#pragma unroll
            for (int ntp = 0; ntp < 4; ntp++) {
                uint32_t bm[4];
                ldsm4t(bm, vBase + (uint32_t)(kc * 16 * KSTRH + ntp * 16) * 2);
                mma_f16(oacc[2 * ntp], pa, bm[0], bm[1]);
                mma_f16(oacc[2 * ntp + 1], pa, bm[2], bm[3]);
            }
        }
        // loop-top __syncthreads orders P reads vs next-tile writes
    }

    // ---- finalize ----
    l0 += __shfl_xor_sync(0xffffffffu, l0, 1);
    l0 += __shfl_xor_sync(0xffffffffu, l0, 2);
    l1 += __shfl_xor_sync(0xffffffffu, l1, 1);
    l1 += __shfl_xor_sync(0xffffffffu, l1, 2);
    const float inv0 = 1.f / l0;
    const float inv1 = 1.f / l1;

    __half* Ob = O + (size_t)b * SEQ * DM + h * HD;
#pragma unroll
    for (int nt = 0; nt < 8; nt++) {
        const int col = nt * 8 + 2 * tk;
        *(uint32_t*)(Ob + (size_t)r0 * DM + col) =
            h2u(__floats2half2_rn(oacc[nt][0] * inv0, oacc[nt][1] * inv0));
        *(uint32_t*)(Ob + (size_t)r1 * DM + col) =
            h2u(__floats2half2_rn(oacc[nt][2] * inv1, oacc[nt][3] * inv1));
    }
}

// ---------------------------------------------------------------------------
// kernel_launch
// ---------------------------------------------------------------------------
extern "C" void kernel_launch(void* const* d_in, const int* in_sizes, int n_in,
                              void* d_out, int out_size)
{
    const float* xq = (const float*)d_in[0];
    const float* xk = (const float*)d_in[1];
    const float* xv = (const float*)d_in[2];
    const float* Wq = (const float*)d_in[3];
    const float* bq = (const float*)d_in[4];
    const float* Wk = (const float*)d_in[5];
    const float* bk = (const float*)d_in[6];
    const float* Wv = (const float*)d_in[7];
    const float* bv = (const float*)d_in[8];
    const float* Wo = (const float*)d_in[9];
    const float* bo = (const float*)d_in[10];
    float* out = (float*)d_out;

    __half *Qh, *Kh, *Vh, *Ch, *Xq, *Xk, *Xv, *Wt;
    cudaGetSymbolAddress((void**)&Qh, g_Qh);
    cudaGetSymbolAddress((void**)&Kh, g_Kh);
    cudaGetSymbolAddress((void**)&Vh, g_Vh);
    cudaGetSymbolAddress((void**)&Ch, g_Ch);
    cudaGetSymbolAddress((void**)&Xq, g_Xq);
    cudaGetSymbolAddress((void**)&Xk, g_Xk);
    cudaGetSymbolAddress((void**)&Xv, g_Xv);
    cudaGetSymbolAddress((void**)&Wt, g_Wt);

    cudaFuncSetAttribute(gemm_h<__half>, cudaFuncAttributeMaxDynamicSharedMemorySize,
                         GSMEMH);
    cudaFuncSetAttribute(gemm_h<float>, cudaFuncAttributeMaxDynamicSharedMemorySize,
                         GSMEMH);
    cudaFuncSetAttribute(attn_h, cudaFuncAttributeMaxDynamicSharedMemorySize,
                         ATTNH_SMEM);

    const int cblk = MR * DM / 8 / 256;     // 4096
    const dim3 tg(32, 32), tb(32, 8);
    const dim3 gg(DM / 128, MR / 128);      // (8, 64)

    // pre-pass: inputs -> half, weights -> transposed half
    conv_h<<<cblk, 256>>>(xq, Xq);
    conv_h<<<cblk, 256>>>(xk, Xk);
    conv_h<<<cblk, 256>>>(xv, Xv);
    wtrans_h<<<tg, tb>>>(Wq, Wt + 0 * (size_t)DM * DM);
    wtrans_h<<<tg, tb>>>(Wk, Wt + 1 * (size_t)DM * DM);
    wtrans_h<<<tg, tb>>>(Wv, Wt + 2 * (size_t)DM * DM);
    wtrans_h<<<tg, tb>>>(Wo, Wt + 3 * (size_t)DM * DM);

    // projections
    gemm_h<__half><<<gg, 256, GSMEMH>>>(Xq, Wt + 0 * (size_t)DM * DM, bq, Qh);
    gemm_h<__half><<<gg, 256, GSMEMH>>>(Xk, Wt + 1 * (size_t)DM * DM, bk, Kh);
    gemm_h<__half><<<gg, 256, GSMEMH>>>(Xv, Wt + 2 * (size_t)DM * DM, bv, Vh);

    // causal attention
    attn_h<<<dim3(SEQ / 128, BATCH * NH), 256, ATTNH_SMEM>>>(Qh, Kh, Vh, Ch);

    // output projection (fp32 out)
    gemm_h<float><<<gg, 256, GSMEMH>>>(Ch, Wt + 3 * (size_t)DM * DM, bo, out);
}

// round 14
// speedup vs baseline: 7.2199x; 1.0765x over previous
#include <cuda_runtime.h>
#include <cuda_fp16.h>
#include <cstdint>

#define DM 1024
#define NH 16
#define HD 64
#define BATCH 4
#define SEQ 2048
#define MR (BATCH*SEQ)

// ---------------------------------------------------------------------------
// Scratch (static device globals -- no allocation allowed)
// ---------------------------------------------------------------------------
__device__ __half g_Qh[MR * DM];      // Q projection (half)
__device__ __half g_Kh[MR * DM];      // K projection
__device__ __half g_Vh[MR * DM];      // V projection
__device__ __half g_Ch[MR * DM];      // attention context
__device__ __half g_Xq[MR * DM];      // half-converted inputs
__device__ __half g_Xk[MR * DM];
__device__ __half g_Xv[MR * DM];
__device__ __half g_Wt[4][DM * DM];   // transposed half weights Wt[n][k] = W[k][n]

// ---------------------------------------------------------------------------
// Helpers
// ---------------------------------------------------------------------------
__device__ __forceinline__ uint32_t smem_u32(const void* p) {
    uint32_t a;
    asm("{ .reg .u64 t; cvta.to.shared.u64 t, %1; cvt.u32.u64 %0, t; }"
        : "=r"(a) : "l"(p));
    return a;
}
__device__ __forceinline__ void cp16(uint32_t dst, const void* src) {
    asm volatile("cp.async.cg.shared.global [%0], [%1], 16;" :: "r"(dst), "l"(src));
}
__device__ __forceinline__ void cp_commit() {
    asm volatile("cp.async.commit_group;" ::: "memory");
}
template <int N>
__device__ __forceinline__ void cp_wait() {
    asm volatile("cp.async.wait_group %0;" :: "n"(N) : "memory");
}
__device__ __forceinline__ float ex2(float x) {
    float y;
    asm("ex2.approx.ftz.f32 %0, %1;" : "=f"(y) : "f"(x));
    return y;
}
__device__ __forceinline__ void mma_f16(float* c, const uint32_t* a,
                                        uint32_t b0, uint32_t b1) {
    asm volatile(
        "mma.sync.aligned.m16n8k16.row.col.f32.f16.f16.f32 "
        "{%0,%1,%2,%3}, {%4,%5,%6,%7}, {%8,%9}, {%0,%1,%2,%3};"
        : "+f"(c[0]), "+f"(c[1]), "+f"(c[2]), "+f"(c[3])
        : "r"(a[0]), "r"(a[1]), "r"(a[2]), "r"(a[3]), "r"(b0), "r"(b1));
}
__device__ __forceinline__ void ldsm4(uint32_t* d, uint32_t a) {
    asm volatile("ldmatrix.sync.aligned.m8n8.x4.shared.b16 {%0,%1,%2,%3}, [%4];"
                 : "=r"(d[0]), "=r"(d[1]), "=r"(d[2]), "=r"(d[3]) : "r"(a));
}
__device__ __forceinline__ void ldsm4t(uint32_t* d, uint32_t a) {
    asm volatile("ldmatrix.sync.aligned.m8n8.x4.trans.shared.b16 {%0,%1,%2,%3}, [%4];"
                 : "=r"(d[0]), "=r"(d[1]), "=r"(d[2]), "=r"(d[3]) : "r"(a));
}
__device__ __forceinline__ uint32_t h2u(__half2 v) {
    return *reinterpret_cast<uint32_t*>(&v);
}

// ---------------------------------------------------------------------------
// fp32 -> fp16 conversion, 3 tensors in one launch (blockIdx.y selects)
// ---------------------------------------------------------------------------
__global__ __launch_bounds__(256)
void conv_h3(const float* __restrict__ i0, const float* __restrict__ i1,
             const float* __restrict__ i2, __half* __restrict__ o0,
             __half* __restrict__ o1, __half* __restrict__ o2) {
    const float* in = (blockIdx.y == 0) ? i0 : (blockIdx.y == 1) ? i1 : i2;
    __half* out = (blockIdx.y == 0) ? o0 : (blockIdx.y == 1) ? o1 : o2;
    const int i = (blockIdx.x * 256 + threadIdx.x) * 8;
    const float4 a = *(const float4*)(in + i);
    const float4 b = *(const float4*)(in + i + 4);
    uint4 u = make_uint4(h2u(__floats2half2_rn(a.x, a.y)),
                         h2u(__floats2half2_rn(a.z, a.w)),
                         h2u(__floats2half2_rn(b.x, b.y)),
                         h2u(__floats2half2_rn(b.z, b.w)));
    *(uint4*)(out + i) = u;
}

// ---------------------------------------------------------------------------
// W[K,N] fp32 -> Wt[N,K] fp16 transpose, 4 weights in one launch (blockIdx.z)
// ---------------------------------------------------------------------------
__global__ __launch_bounds__(256)
void wtrans4(const float* __restrict__ w0, const float* __restrict__ w1,
             const float* __restrict__ w2, const float* __restrict__ w3,
             __half* __restrict__ Wt) {
    const float* W = (blockIdx.z == 0) ? w0 : (blockIdx.z == 1) ? w1
                   : (blockIdx.z == 2) ? w2 : w3;
    __half* out = Wt + (size_t)blockIdx.z * DM * DM;
    __shared__ float t[32][33];
    const int bx = blockIdx.x * 32, by = blockIdx.y * 32;
    const int tx = threadIdx.x, ty = threadIdx.y;
#pragma unroll
    for (int i = 0; i < 4; i++)
        t[ty + 8 * i][tx] = W[(size_t)(by + ty + 8 * i) * DM + bx + tx];
    __syncthreads();
#pragma unroll
    for (int i = 0; i < 4; i++)
        out[(size_t)(bx + ty + 8 * i) * DM + by + tx] = __float2half_rn(t[tx][ty + 8 * i]);
}

// ---------------------------------------------------------------------------
// fp16 tensor-core GEMM: C[8192,1024] = A[M,K] @ Wt[N,K]^T + bias
// (unchanged from R12 passing kernel)
// ---------------------------------------------------------------------------
#define ASTRH 40
#define GSTG  (2 * 128 * ASTRH)
#define GSMEMH (2 * GSTG * 2)
#define GNITER (DM / 32)

template <typename OUT>
__global__ __launch_bounds__(256, 2)
void gemm_h(const __half* __restrict__ A, const __half* __restrict__ Wt,
            const float* __restrict__ bias, OUT* __restrict__ C)
{
    extern __shared__ __half shh[];
    const uint32_t smb = smem_u32(shh);

    const int tid = threadIdx.x;
    const int wid = tid >> 5;
    const int lane = tid & 31;
    const int tr = lane >> 2;
    const int tk = lane & 3;
    const int wm = wid >> 2;
    const int wn = wid & 3;
    const int br = blockIdx.y, bc = blockIdx.x;

    const __half* Ab = A + (size_t)br * 128 * DM;
    const __half* Wb = Wt + (size_t)bc * 128 * DM;

    float acc[4][4][4];
#pragma unroll
    for (int mt = 0; mt < 4; mt++)
#pragma unroll
        for (int nt = 0; nt < 4; nt++)
#pragma unroll
            for (int c = 0; c < 4; c++) acc[mt][nt][c] = 0.f;

    auto load_stage = [&](int s, int k0) {
        const uint32_t aB = smb + (uint32_t)(s * GSTG) * 2;
        const uint32_t wB = aB + 128 * ASTRH * 2;
#pragma unroll
        for (int j = 0; j < 2; j++) {
            const int idx = j * 256 + tid;
            const int row = idx >> 2;
            const int c = idx & 3;
            cp16(aB + (uint32_t)(row * ASTRH + c * 8) * 2,
                 Ab + (size_t)row * DM + k0 + c * 8);
        }
#pragma unroll
        for (int j = 0; j < 2; j++) {
            const int idx = j * 256 + tid;
            const int row = idx >> 2;
            const int c = idx & 3;
            cp16(wB + (uint32_t)(row * ASTRH + c * 8) * 2,
                 Wb + (size_t)row * DM + k0 + c * 8);
        }
        cp_commit();
    };

    load_stage(0, 0);

    for (int i = 0; i < GNITER; i++) {
        if (i + 1 < GNITER) {
            load_stage((i + 1) & 1, (i + 1) * 32);
            cp_wait<1>();
        } else {
            cp_wait<0>();
        }
        __syncthreads();

        const __half* as = shh + (i & 1) * GSTG;
        const __half* ws = as + 128 * ASTRH;

#pragma unroll
        for (int ks = 0; ks < 2; ks++) {
            const int kb = ks * 16 + 2 * tk;
            uint32_t af[4][4], bf[4][2];
#pragma unroll
            for (int mt = 0; mt < 4; mt++) {
                const __half* p = as + (wm * 64 + mt * 16 + tr) * ASTRH + kb;
                af[mt][0] = *(const uint32_t*)p;
                af[mt][1] = *(const uint32_t*)(p + 8 * ASTRH);
                af[mt][2] = *(const uint32_t*)(p + 8);
                af[mt][3] = *(const uint32_t*)(p + 8 * ASTRH + 8);
            }
#pragma unroll
            for (int nt = 0; nt < 4; nt++) {
                const __half* p = ws + (wn * 32 + nt * 8 + tr) * ASTRH + kb;
                bf[nt][0] = *(const uint32_t*)p;
                bf[nt][1] = *(const uint32_t*)(p + 8);
            }
#pragma unroll
            for (int mt = 0; mt < 4; mt++)
#pragma unroll
                for (int nt = 0; nt < 4; nt++)
                    mma_f16(acc[mt][nt], af[mt], bf[nt][0], bf[nt][1]);
        }
        __syncthreads();
    }

#pragma unroll
    for (int mt = 0; mt < 4; mt++) {
        const int row = br * 128 + wm * 64 + mt * 16 + tr;
#pragma unroll
        for (int nt = 0; nt < 4; nt++) {
            const int col = bc * 128 + wn * 32 + nt * 8 + 2 * tk;
            const float2 bv = *(const float2*)(bias + col);
            const float v0 = acc[mt][nt][0] + bv.x;
            const float v1 = acc[mt][nt][1] + bv.y;
            const float v2 = acc[mt][nt][2] + bv.x;
            const float v3 = acc[mt][nt][3] + bv.y;
            if constexpr (sizeof(OUT) == 4) {
                *(float2*)((float*)C + (size_t)row * DM + col) = make_float2(v0, v1);
                *(float2*)((float*)C + (size_t)(row + 8) * DM + col) = make_float2(v2, v3);
            } else {
                *(uint32_t*)((__half*)C + (size_t)row * DM + col) =
                    h2u(__floats2half2_rn(v0, v1));
                *(uint32_t*)((__half*)C + (size_t)(row + 8) * DM + col) =
                    h2u(__floats2half2_rn(v2, v3));
            }
        }
    }
}

// ---------------------------------------------------------------------------
// fp16 tensor-core causal flash attention (register-P, 4-stage cp.async)
// 8 warps x 16 q-rows = 128 q / block; 64-key tiles; one syncthreads/tile.
// smem: 4 stages x (Ks[64][72] + Vs[64][72]) halves = 73728 bytes
// ---------------------------------------------------------------------------
#define KSTRH 72
#define AT_STG (2 * 64 * KSTRH)              // halves per stage
#define ATTNH_SMEM (4 * AT_STG * 2)          // 73728 bytes

__global__ __launch_bounds__(256, 2)
void attn_h(const __half* __restrict__ Q, const __half* __restrict__ K,
            const __half* __restrict__ V, __half* __restrict__ O)
{
    extern __shared__ __half sh2[];
    const uint32_t smb = smem_u32(sh2);
    const int tid = threadIdx.x;
    const int wid = tid >> 5;
    const int lane = tid & 31;
    const int tr = lane >> 2;
    const int tk = lane & 3;
    const int qb = (SEQ / 128 - 1) - blockIdx.x;    // heavy blocks first
    const int b = blockIdx.y >> 4;
    const int h = blockIdx.y & 15;

    // ldmatrix per-thread address offsets (within a stage)
    const int r8 = lane & 7;
    const int b3 = (lane >> 3) & 1;
    const int b4 = (lane >> 4) & 1;
    const uint32_t kOff = (uint32_t)((b4 * 8 + r8) * KSTRH + b3 * 8) * 2;
    const uint32_t vOff = (uint32_t)(64 * KSTRH + (r8 + b3 * 8) * KSTRH + b4 * 8) * 2;

    const int r0 = qb * 128 + wid * 16 + tr;
    const int r1 = r0 + 8;

    const __half* Kbh = K + (size_t)b * SEQ * DM + h * HD;
    const __half* Vbh = V + (size_t)b * SEQ * DM + h * HD;
    const int ntiles = 2 * (qb + 1);

    // per-stage K/V tile load via cp.async (16KB K + 16KB V)
    auto load_stage = [&](int s, int kt) {
        const uint32_t base = smb + (uint32_t)(s * AT_STG) * 2;
#pragma unroll
        for (int j = 0; j < 2; j++) {
            const int idx = j * 256 + tid;       // 0..511
            const int key = idx >> 3;            // 0..63
            const int c = idx & 7;               // 8-half chunk
            const size_t go = (size_t)(kt * 64 + key) * DM + c * 8;
            cp16(base + (uint32_t)(key * KSTRH + c * 8) * 2, Kbh + go);
            cp16(base + (uint32_t)((64 + key) * KSTRH + c * 8) * 2, Vbh + go);
        }
        cp_commit();
    };

    // prologue: start 2 tiles, then load Q fragments (overlaps with cp.async)
    load_stage(0, 0);
    if (ntiles > 1) load_stage(1, 1);

    const float qs = 0.125f * 1.4426950408889634f;
    const __half* Qbh = Q + (size_t)b * SEQ * DM + h * HD;
    uint32_t qf[4][4];
#pragma unroll
    for (int kc = 0; kc < 4; kc++) {
        const __half* p0 = Qbh + (size_t)r0 * DM + kc * 16 + 2 * tk;
        const __half* p1 = Qbh + (size_t)r1 * DM + kc * 16 + 2 * tk;
#pragma unroll
        for (int j = 0; j < 4; j++) {
            const __half* p = (j & 1) ? p1 : p0;
            const float2 f = __half22float2(*(const __half2*)(p + (j >> 1) * 8));
            qf[kc][j] = h2u(__floats2half2_rn(f.x * qs, f.y * qs));
        }
    }

    float oacc[8][4];
#pragma unroll
    for (int nt = 0; nt < 8; nt++)
#pragma unroll
        for (int c = 0; c < 4; c++) oacc[nt][c] = 0.f;
    float m0 = -1e30f, m1 = -1e30f, l0 = 0.f, l1 = 0.f;

    for (int kt = 0; kt < ntiles; kt++) {
        // issue load 2 tiles ahead; target stage last read 2 iterations ago
        if (kt + 2 < ntiles) {
            load_stage((kt + 2) & 3, kt + 2);
            cp_wait<2>();
        } else if (kt + 1 < ntiles) {
            cp_wait<1>();
        } else {
            cp_wait<0>();
        }
        __syncthreads();

        const uint32_t stg = smb + (uint32_t)(((kt & 3) * AT_STG) * 2);
        const uint32_t kBase = stg + kOff;
        const uint32_t vBase = stg + vOff;

        // ---- S = Q @ K^T ----
        float sacc[8][4];
#pragma unroll
        for (int nt = 0; nt < 8; nt++)
#pragma unroll
            for (int c = 0; c < 4; c++) sacc[nt][c] = 0.f;

#pragma unroll
        for (int kc = 0; kc < 4; kc++) {
#pragma unroll
            for (int ntp = 0; ntp < 4; ntp++) {
                uint32_t bm[4];
                ldsm4(bm, kBase + (uint32_t)(ntp * 16 * KSTRH + kc * 16) * 2);
                mma_f16(sacc[2 * ntp], qf[kc], bm[0], bm[1]);
                mma_f16(sacc[2 * ntp + 1], qf[kc], bm[2], bm[3]);
            }
        }

        // ---- causal mask (diagonal tiles only) ----
        if (kt >= 2 * qb) {
#pragma unroll
            for (int nt = 0; nt < 8; nt++) {
                const int c0 = kt * 64 + nt * 8 + 2 * tk;
                if (c0 > r0)     sacc[nt][0] = -1e30f;
                if (c0 + 1 > r0) sacc[nt][1] = -1e30f;
                if (c0 > r1)     sacc[nt][2] = -1e30f;
                if (c0 + 1 > r1) sacc[nt][3] = -1e30f;
            }
        }

        // ---- online softmax ----
        float mn0 = m0, mn1 = m1;
#pragma unroll
        for (int nt = 0; nt < 8; nt++) {
            mn0 = fmaxf(mn0, fmaxf(sacc[nt][0], sacc[nt][1]));
            mn1 = fmaxf(mn1, fmaxf(sacc[nt][2], sacc[nt][3]));
        }
        mn0 = fmaxf(mn0, __shfl_xor_sync(0xffffffffu, mn0, 1));
        mn0 = fmaxf(mn0, __shfl_xor_sync(0xffffffffu, mn0, 2));
        mn1 = fmaxf(mn1, __shfl_xor_sync(0xffffffffu, mn1, 1));
        mn1 = fmaxf(mn1, __shfl_xor_sync(0xffffffffu, mn1, 2));

        const float cr0 = ex2(m0 - mn0);
        const float cr1 = ex2(m1 - mn1);
        m0 = mn0; m1 = mn1;
        l0 *= cr0; l1 *= cr1;
#pragma unroll
        for (int nt = 0; nt < 8; nt++) {
            oacc[nt][0] *= cr0; oacc[nt][1] *= cr0;
            oacc[nt][2] *= cr1; oacc[nt][3] *= cr1;
        }

        // ---- P in registers: pack probabilities as half2 A-fragments ----
        uint32_t ph[8][2];
#pragma unroll
        for (int nt = 0; nt < 8; nt++) {
            const float p0 = ex2(sacc[nt][0] - m0);
            const float p1 = ex2(sacc[nt][1] - m0);
            const float p2 = ex2(sacc[nt][2] - m1);
            const float p3 = ex2(sacc[nt][3] - m1);
            l0 += p0 + p1;
            l1 += p2 + p3;
            ph[nt][0] = h2u(__floats2half2_rn(p0, p1));
            ph[nt][1] = h2u(__floats2half2_rn(p2, p3));
        }

        // ---- O += P @ V; A-frag from registers (FA2 layout identity) ----
#pragma unroll
        for (int kk = 0; kk < 4; kk++) {
            uint32_t pa[4];
            pa[0] = ph[2 * kk][0];
            pa[1] = ph[2 * kk][1];
            pa[2] = ph[2 * kk + 1][0];
            pa[3] = ph[2 * kk + 1][1];
#pragma unroll
            for (int ntp = 0; ntp < 4; ntp++) {
                uint32_t bm[4];
                ldsm4t(bm, vBase + (uint32_t)(kk * 16 * KSTRH + ntp * 16) * 2);
                mma_f16(oacc[2 * ntp], pa, bm[0], bm[1]);
                mma_f16(oacc[2 * ntp + 1], pa, bm[2], bm[3]);
            }
        }
    }

    // ---- finalize ----
    l0 += __shfl_xor_sync(0xffffffffu, l0, 1);
    l0 += __shfl_xor_sync(0xffffffffu, l0, 2);
    l1 += __shfl_xor_sync(0xffffffffu, l1, 1);
    l1 += __shfl_xor_sync(0xffffffffu, l1, 2);
    const float inv0 = 1.f / l0;
    const float inv1 = 1.f / l1;

    __half* Ob = O + (size_t)b * SEQ * DM + h * HD;
#pragma unroll
    for (int nt = 0; nt < 8; nt++) {
        const int col = nt * 8 + 2 * tk;
        *(uint32_t*)(Ob + (size_t)r0 * DM + col) =
            h2u(__floats2half2_rn(oacc[nt][0] * inv0, oacc[nt][1] * inv0));
        *(uint32_t*)(Ob + (size_t)r1 * DM + col) =
            h2u(__floats2half2_rn(oacc[nt][2] * inv1, oacc[nt][3] * inv1));
    }
}

// ---------------------------------------------------------------------------
// kernel_launch
// ---------------------------------------------------------------------------
extern "C" void kernel_launch(void* const* d_in, const int* in_sizes, int n_in,
                              void* d_out, int out_size)
{
    const float* xq = (const float*)d_in[0];
    const float* xk = (const float*)d_in[1];
    const float* xv = (const float*)d_in[2];
    const float* Wq = (const float*)d_in[3];
    const float* bq = (const float*)d_in[4];
    const float* Wk = (const float*)d_in[5];
    const float* bk = (const float*)d_in[6];
    const float* Wv = (const float*)d_in[7];
    const float* bv = (const float*)d_in[8];
    const float* Wo = (const float*)d_in[9];
    const float* bo = (const float*)d_in[10];
    float* out = (float*)d_out;

    __half *Qh, *Kh, *Vh, *Ch, *Xq, *Xk, *Xv, *Wt;
    cudaGetSymbolAddress((void**)&Qh, g_Qh);
    cudaGetSymbolAddress((void**)&Kh, g_Kh);
    cudaGetSymbolAddress((void**)&Vh, g_Vh);
    cudaGetSymbolAddress((void**)&Ch, g_Ch);
    cudaGetSymbolAddress((void**)&Xq, g_Xq);
    cudaGetSymbolAddress((void**)&Xk, g_Xk);
    cudaGetSymbolAddress((void**)&Xv, g_Xv);
    cudaGetSymbolAddress((void**)&Wt, g_Wt);

    cudaFuncSetAttribute(gemm_h<__half>, cudaFuncAttributeMaxDynamicSharedMemorySize,
                         GSMEMH);
    cudaFuncSetAttribute(gemm_h<float>, cudaFuncAttributeMaxDynamicSharedMemorySize,
                         GSMEMH);
    cudaFuncSetAttribute(attn_h, cudaFuncAttributeMaxDynamicSharedMemorySize,
                         ATTNH_SMEM);

    const int cblk = MR * DM / 8 / 256;     // 4096
    const dim3 gg(DM / 128, MR / 128);      // (8, 64)

    // pre-pass: inputs -> half (1 launch), weights -> transposed half (1 launch)
    conv_h3<<<dim3(cblk, 3), 256>>>(xq, xk, xv, Xq, Xk, Xv);
    wtrans4<<<dim3(32, 32, 4), dim3(32, 8)>>>(Wq, Wk, Wv, Wo, Wt);

    // projections
    gemm_h<__half><<<gg, 256, GSMEMH>>>(Xq, Wt + 0 * (size_t)DM * DM, bq, Qh);
    gemm_h<__half><<<gg, 256, GSMEMH>>>(Xk, Wt + 1 * (size_t)DM * DM, bk, Kh);
    gemm_h<__half><<<gg, 256, GSMEMH>>>(Xv, Wt + 2 * (size_t)DM * DM, bv, Vh);

    // causal attention
    attn_h<<<dim3(SEQ / 128, BATCH * NH), 256, ATTNH_SMEM>>>(Qh, Kh, Vh, Ch);

    // output projection (fp32 out)
    gemm_h<float><<<gg, 256, GSMEMH>>>(Ch, Wt + 3 * (size_t)DM * DM, bo, out);
}

// round 15
// speedup vs baseline: 8.7695x; 1.2146x over previous
#include <cuda_runtime.h>
#include <cuda_fp16.h>
#include <cstdint>

#define DM 1024
#define NH 16
#define HD 64
#define BATCH 4
#define SEQ 2048
#define MR (BATCH*SEQ)

// ---------------------------------------------------------------------------
// Scratch (static device globals -- no allocation allowed)
// ---------------------------------------------------------------------------
__device__ __half g_Qh[MR * DM];      // Q projection (half)
__device__ __half g_Kh[MR * DM];      // K projection
__device__ __half g_Vh[MR * DM];      // V projection
__device__ __half g_Ch[MR * DM];      // attention context
__device__ __half g_Xq[MR * DM];      // half-converted inputs
__device__ __half g_Xk[MR * DM];
__device__ __half g_Xv[MR * DM];
__device__ __half g_Wt[4][DM * DM];   // transposed half weights Wt[n][k] = W[k][n]

// ---------------------------------------------------------------------------
// Helpers
// ---------------------------------------------------------------------------
__device__ __forceinline__ uint32_t smem_u32(const void* p) {
    uint32_t a;
    asm("{ .reg .u64 t; cvta.to.shared.u64 t, %1; cvt.u32.u64 %0, t; }"
        : "=r"(a) : "l"(p));
    return a;
}
__device__ __forceinline__ void cp16(uint32_t dst, const void* src) {
    asm volatile("cp.async.cg.shared.global [%0], [%1], 16;" :: "r"(dst), "l"(src));
}
__device__ __forceinline__ void cp_commit() {
    asm volatile("cp.async.commit_group;" ::: "memory");
}
template <int N>
__device__ __forceinline__ void cp_wait() {
    asm volatile("cp.async.wait_group %0;" :: "n"(N) : "memory");
}
__device__ __forceinline__ float ex2(float x) {
    float y;
    asm("ex2.approx.ftz.f32 %0, %1;" : "=f"(y) : "f"(x));
    return y;
}
__device__ __forceinline__ void mma_f16(float* c, const uint32_t* a,
                                        uint32_t b0, uint32_t b1) {
    asm volatile(
        "mma.sync.aligned.m16n8k16.row.col.f32.f16.f16.f32 "
        "{%0,%1,%2,%3}, {%4,%5,%6,%7}, {%8,%9}, {%0,%1,%2,%3};"
        : "+f"(c[0]), "+f"(c[1]), "+f"(c[2]), "+f"(c[3])
        : "r"(a[0]), "r"(a[1]), "r"(a[2]), "r"(a[3]), "r"(b0), "r"(b1));
}
__device__ __forceinline__ void ldsm4(uint32_t* d, uint32_t a) {
    asm volatile("ldmatrix.sync.aligned.m8n8.x4.shared.b16 {%0,%1,%2,%3}, [%4];"
                 : "=r"(d[0]), "=r"(d[1]), "=r"(d[2]), "=r"(d[3]) : "r"(a));
}
__device__ __forceinline__ void ldsm4t(uint32_t* d, uint32_t a) {
    asm volatile("ldmatrix.sync.aligned.m8n8.x4.trans.shared.b16 {%0,%1,%2,%3}, [%4];"
                 : "=r"(d[0]), "=r"(d[1]), "=r"(d[2]), "=r"(d[3]) : "r"(a));
}
__device__ __forceinline__ uint32_t h2u(__half2 v) {
    return *reinterpret_cast<uint32_t*>(&v);
}

// ---------------------------------------------------------------------------
// fp32 -> fp16 conversion, 3 tensors in one launch (blockIdx.y selects)
// ---------------------------------------------------------------------------
__global__ __launch_bounds__(256)
void conv_h3(const float* __restrict__ i0, const float* __restrict__ i1,
             const float* __restrict__ i2, __half* __restrict__ o0,
             __half* __restrict__ o1, __half* __restrict__ o2) {
    const float* in = (blockIdx.y == 0) ? i0 : (blockIdx.y == 1) ? i1 : i2;
    __half* out = (blockIdx.y == 0) ? o0 : (blockIdx.y == 1) ? o1 : o2;
    const int i = (blockIdx.x * 256 + threadIdx.x) * 8;
    const float4 a = *(const float4*)(in + i);
    const float4 b = *(const float4*)(in + i + 4);
    uint4 u = make_uint4(h2u(__floats2half2_rn(a.x, a.y)),
                         h2u(__floats2half2_rn(a.z, a.w)),
                         h2u(__floats2half2_rn(b.x, b.y)),
                         h2u(__floats2half2_rn(b.z, b.w)));
    *(uint4*)(out + i) = u;
}

// ---------------------------------------------------------------------------
// W[K,N] fp32 -> Wt[N,K] fp16 transpose, 4 weights in one launch (blockIdx.z)
// ---------------------------------------------------------------------------
__global__ __launch_bounds__(256)
void wtrans4(const float* __restrict__ w0, const float* __restrict__ w1,
             const float* __restrict__ w2, const float* __restrict__ w3,
             __half* __restrict__ Wt) {
    const float* W = (blockIdx.z == 0) ? w0 : (blockIdx.z == 1) ? w1
                   : (blockIdx.z == 2) ? w2 : w3;
    __half* out = Wt + (size_t)blockIdx.z * DM * DM;
    __shared__ float t[32][33];
    const int bx = blockIdx.x * 32, by = blockIdx.y * 32;
    const int tx = threadIdx.x, ty = threadIdx.y;
#pragma unroll
    for (int i = 0; i < 4; i++)
        t[ty + 8 * i][tx] = W[(size_t)(by + ty + 8 * i) * DM + bx + tx];
    __syncthreads();
#pragma unroll
    for (int i = 0; i < 4; i++)
        out[(size_t)(bx + ty + 8 * i) * DM + by + tx] = __float2half_rn(t[tx][ty + 8 * i]);
}

// ---------------------------------------------------------------------------
// fp16 tensor-core GEMM core: C[8192,1024] = A[M,K] @ Wt[N,K]^T + bias
// CTA 128x128x64, 256 thr, warp 64x32, ldmatrix fragments, double buffer.
// ---------------------------------------------------------------------------
#define ASTRH 72                          // halves per smem row (144B, LDSM-safe)
#define GSTG  (2 * 128 * ASTRH)           // halves per stage (A 128x64 + B 128x64)
#define GSMEMH (2 * GSTG * 2)             // 73728 bytes
#define GNITER (DM / 64)                  // 16

template <typename OUT>
__device__ __forceinline__
void gemm_core(const __half* __restrict__ A, const __half* __restrict__ Wt,
               const float* __restrict__ bias, OUT* __restrict__ C,
               __half* shh)
{
    const uint32_t smb = smem_u32(shh);

    const int tid = threadIdx.x;
    const int wid = tid >> 5;
    const int lane = tid & 31;
    const int tr = lane >> 2;
    const int tk = lane & 3;
    const int wm = wid >> 2;        // 0..1
    const int wn = wid & 3;         // 0..3
    const int br = blockIdx.y, bc = blockIdx.x;

    const __half* Ab = A + (size_t)br * 128 * DM;
    const __half* Wb = Wt + (size_t)bc * 128 * DM;

    // ldmatrix lane-address offsets (bytes, within a stage half)
    // A (x4): m0 rows0-7 k0-7, m1 rows8-15 k0-7, m2 rows0-7 k8-15, m3 rows8-15 k8-15
    const uint32_t aLane = (uint32_t)((lane & 15) * ASTRH + ((lane >> 4) << 3)) * 2;
    // B (x4): m0 n0-7 k0-7, m1 n0-7 k8-15, m2 n8-15 k0-7, m3 n8-15 k8-15
    const uint32_t bLane = (uint32_t)(((((lane >> 4) & 1) << 3) + (lane & 7)) * ASTRH
                                      + (((lane >> 3) & 1) << 3)) * 2;

    float acc[4][4][4];
#pragma unroll
    for (int mt = 0; mt < 4; mt++)
#pragma unroll
        for (int nt = 0; nt < 4; nt++)
#pragma unroll
            for (int c = 0; c < 4; c++) acc[mt][nt][c] = 0.f;

    auto load_stage = [&](int s, int k0) {
        const uint32_t aB = smb + (uint32_t)(s * GSTG) * 2;
        const uint32_t wB = aB + 128 * ASTRH * 2;
#pragma unroll
        for (int j = 0; j < 4; j++) {
            const int idx = j * 256 + tid;   // 0..1023
            const int row = idx >> 3;        // 0..127
            const int c = idx & 7;           // 8-half chunk within 64
            cp16(aB + (uint32_t)(row * ASTRH + c * 8) * 2,
                 Ab + (size_t)row * DM + k0 + c * 8);
        }
#pragma unroll
        for (int j = 0; j < 4; j++) {
            const int idx = j * 256 + tid;
            const int row = idx >> 3;
            const int c = idx & 7;
            cp16(wB + (uint32_t)(row * ASTRH + c * 8) * 2,
                 Wb + (size_t)row * DM + k0 + c * 8);
        }
        cp_commit();
    };

    load_stage(0, 0);

    for (int i = 0; i < GNITER; i++) {
        if (i + 1 < GNITER) {
            load_stage((i + 1) & 1, (i + 1) * 64);
            cp_wait<1>();
        } else {
            cp_wait<0>();
        }
        __syncthreads();

        const uint32_t asB = smb + (uint32_t)(((i & 1) * GSTG) * 2);
        const uint32_t wsB = asB + 128 * ASTRH * 2;
        const uint32_t aWarp = asB + aLane + (uint32_t)(wm * 64 * ASTRH) * 2;
        const uint32_t bWarp = wsB + bLane + (uint32_t)(wn * 32 * ASTRH) * 2;

#pragma unroll
        for (int ks = 0; ks < 4; ks++) {
            const uint32_t kb = (uint32_t)(ks * 16) * 2;
            uint32_t af[4][4], bf[2][4];
#pragma unroll
            for (int mt = 0; mt < 4; mt++)
                ldsm4(af[mt], aWarp + (uint32_t)(mt * 16 * ASTRH) * 2 + kb);
#pragma unroll
            for (int np = 0; np < 2; np++)
                ldsm4(bf[np], bWarp + (uint32_t)(np * 16 * ASTRH) * 2 + kb);
#pragma unroll
            for (int mt = 0; mt < 4; mt++) {
#pragma unroll
                for (int np = 0; np < 2; np++) {
                    mma_f16(acc[mt][2 * np], af[mt], bf[np][0], bf[np][1]);
                    mma_f16(acc[mt][2 * np + 1], af[mt], bf[np][2], bf[np][3]);
                }
            }
        }
        __syncthreads();
    }

    // epilogue: bias in fp32, store fp32 or half2
#pragma unroll
    for (int mt = 0; mt < 4; mt++) {
        const int row = br * 128 + wm * 64 + mt * 16 + tr;
#pragma unroll
        for (int nt = 0; nt < 4; nt++) {
            const int col = bc * 128 + wn * 32 + nt * 8 + 2 * tk;
            const float2 bv = *(const float2*)(bias + col);
            const float v0 = acc[mt][nt][0] + bv.x;
            const float v1 = acc[mt][nt][1] + bv.y;
            const float v2 = acc[mt][nt][2] + bv.x;
            const float v3 = acc[mt][nt][3] + bv.y;
            if constexpr (sizeof(OUT) == 4) {
                *(float2*)((float*)C + (size_t)row * DM + col) = make_float2(v0, v1);
                *(float2*)((float*)C + (size_t)(row + 8) * DM + col) = make_float2(v2, v3);
            } else {
                *(uint32_t*)((__half*)C + (size_t)row * DM + col) =
                    h2u(__floats2half2_rn(v0, v1));
                *(uint32_t*)((__half*)C + (size_t)(row + 8) * DM + col) =
                    h2u(__floats2half2_rn(v2, v3));
            }
        }
    }
}

// Batched Q/K/V projection: blockIdx.z selects the GEMM
__global__ __launch_bounds__(256, 2)
void gemm_qkv(const __half* __restrict__ A0, const __half* __restrict__ A1,
              const __half* __restrict__ A2, const __half* __restrict__ Wt,
              const float* __restrict__ b0, const float* __restrict__ b1,
              const float* __restrict__ b2, __half* __restrict__ C0,
              __half* __restrict__ C1, __half* __restrict__ C2)
{
    extern __shared__ __half shh[];
    const int z = blockIdx.z;
    const __half* A = (z == 0) ? A0 : (z == 1) ? A1 : A2;
    const float* bias = (z == 0) ? b0 : (z == 1) ? b1 : b2;
    __half* C = (z == 0) ? C0 : (z == 1) ? C1 : C2;
    gemm_core<__half>(A, Wt + (size_t)z * DM * DM, bias, C, shh);
}

// Output projection (fp32 out)
__global__ __launch_bounds__(256, 2)
void gemm_out(const __half* __restrict__ A, const __half* __restrict__ Wt,
              const float* __restrict__ bias, float* __restrict__ C)
{
    extern __shared__ __half shh[];
    gemm_core<float>(A, Wt, bias, C, shh);
}

// ---------------------------------------------------------------------------
// fp16 tensor-core causal flash attention (register-P, 4-stage cp.async)
// (unchanged from R13 passing kernel)
// ---------------------------------------------------------------------------
#define KSTRH 72
#define AT_STG (2 * 64 * KSTRH)
#define ATTNH_SMEM (4 * AT_STG * 2)

__global__ __launch_bounds__(256, 2)
void attn_h(const __half* __restrict__ Q, const __half* __restrict__ K,
            const __half* __restrict__ V, __half* __restrict__ O)
{
    extern __shared__ __half sh2[];
    const uint32_t smb = smem_u32(sh2);
    const int tid = threadIdx.x;
    const int wid = tid >> 5;
    const int lane = tid & 31;
    const int tr = lane >> 2;
    const int tk = lane & 3;
    const int qb = (SEQ / 128 - 1) - blockIdx.x;
    const int b = blockIdx.y >> 4;
    const int h = blockIdx.y & 15;

    const int r8 = lane & 7;
    const int b3 = (lane >> 3) & 1;
    const int b4 = (lane >> 4) & 1;
    const uint32_t kOff = (uint32_t)((b4 * 8 + r8) * KSTRH + b3 * 8) * 2;
    const uint32_t vOff = (uint32_t)(64 * KSTRH + (r8 + b3 * 8) * KSTRH + b4 * 8) * 2;

    const int r0 = qb * 128 + wid * 16 + tr;
    const int r1 = r0 + 8;

    const __half* Kbh = K + (size_t)b * SEQ * DM + h * HD;
    const __half* Vbh = V + (size_t)b * SEQ * DM + h * HD;
    const int ntiles = 2 * (qb + 1);

    auto load_stage = [&](int s, int kt) {
        const uint32_t base = smb + (uint32_t)(s * AT_STG) * 2;
#pragma unroll
        for (int j = 0; j < 2; j++) {
            const int idx = j * 256 + tid;
            const int key = idx >> 3;
            const int c = idx & 7;
            const size_t go = (size_t)(kt * 64 + key) * DM + c * 8;
            cp16(base + (uint32_t)(key * KSTRH + c * 8) * 2, Kbh + go);
            cp16(base + (uint32_t)((64 + key) * KSTRH + c * 8) * 2, Vbh + go);
        }
        cp_commit();
    };

    load_stage(0, 0);
    if (ntiles > 1) load_stage(1, 1);

    const float qs = 0.125f * 1.4426950408889634f;
    const __half* Qbh = Q + (size_t)b * SEQ * DM + h * HD;
    uint32_t qf[4][4];
#pragma unroll
    for (int kc = 0; kc < 4; kc++) {
        const __half* p0 = Qbh + (size_t)r0 * DM + kc * 16 + 2 * tk;
        const __half* p1 = Qbh + (size_t)r1 * DM + kc * 16 + 2 * tk;
#pragma unroll
        for (int j = 0; j < 4; j++) {
            const __half* p = (j & 1) ? p1 : p0;
            const float2 f = __half22float2(*(const __half2*)(p + (j >> 1) * 8));
            qf[kc][j] = h2u(__floats2half2_rn(f.x * qs, f.y * qs));
        }
    }

    float oacc[8][4];
#pragma unroll
    for (int nt = 0; nt < 8; nt++)
#pragma unroll
        for (int c = 0; c < 4; c++) oacc[nt][c] = 0.f;
    float m0 = -1e30f, m1 = -1e30f, l0 = 0.f, l1 = 0.f;

    for (int kt = 0; kt < ntiles; kt++) {
        if (kt + 2 < ntiles) {
            load_stage((kt + 2) & 3, kt + 2);
            cp_wait<2>();
        } else if (kt + 1 < ntiles) {
            cp_wait<1>();
        } else {
            cp_wait<0>();
        }
        __syncthreads();

        const uint32_t stg = smb + (uint32_t)(((kt & 3) * AT_STG) * 2);
        const uint32_t kBase = stg + kOff;
        const uint32_t vBase = stg + vOff;

        float sacc[8][4];
#pragma unroll
        for (int nt = 0; nt < 8; nt++)
#pragma unroll
            for (int c = 0; c < 4; c++) sacc[nt][c] = 0.f;

#pragma unroll
        for (int kc = 0; kc < 4; kc++) {
#pragma unroll
            for (int ntp = 0; ntp < 4; ntp++) {
                uint32_t bm[4];
                ldsm4(bm, kBase + (uint32_t)(ntp * 16 * KSTRH + kc * 16) * 2);
                mma_f16(sacc[2 * ntp], qf[kc], bm[0], bm[1]);
                mma_f16(sacc[2 * ntp + 1], qf[kc], bm[2], bm[3]);
            }
        }

        if (kt >= 2 * qb) {
#pragma unroll
            for (int nt = 0; nt < 8; nt++) {
                const int c0 = kt * 64 + nt * 8 + 2 * tk;
                if (c0 > r0)     sacc[nt][0] = -1e30f;
                if (c0 + 1 > r0) sacc[nt][1] = -1e30f;
                if (c0 > r1)     sacc[nt][2] = -1e30f;
                if (c0 + 1 > r1) sacc[nt][3] = -1e30f;
            }
        }

        float mn0 = m0, mn1 = m1;
#pragma unroll
        for (int nt = 0; nt < 8; nt++) {
            mn0 = fmaxf(mn0, fmaxf(sacc[nt][0], sacc[nt][1]));
            mn1 = fmaxf(mn1, fmaxf(sacc[nt][2], sacc[nt][3]));
        }
        mn0 = fmaxf(mn0, __shfl_xor_sync(0xffffffffu, mn0, 1));
        mn0 = fmaxf(mn0, __shfl_xor_sync(0xffffffffu, mn0, 2));
        mn1 = fmaxf(mn1, __shfl_xor_sync(0xffffffffu, mn1, 1));
        mn1 = fmaxf(mn1, __shfl_xor_sync(0xffffffffu, mn1, 2));

        const float cr0 = ex2(m0 - mn0);
        const float cr1 = ex2(m1 - mn1);
        m0 = mn0; m1 = mn1;
        l0 *= cr0; l1 *= cr1;
#pragma unroll
        for (int nt = 0; nt < 8; nt++) {
            oacc[nt][0] *= cr0; oacc[nt][1] *= cr0;
            oacc[nt][2] *= cr1; oacc[nt][3] *= cr1;
        }

        uint32_t ph[8][2];
#pragma unroll
        for (int nt = 0; nt < 8; nt++) {
            const float p0 = ex2(sacc[nt][0] - m0);
            const float p1 = ex2(sacc[nt][1] - m0);
            const float p2 = ex2(sacc[nt][2] - m1);
            const float p3 = ex2(sacc[nt][3] - m1);
            l0 += p0 + p1;
            l1 += p2 + p3;
            ph[nt][0] = h2u(__floats2half2_rn(p0, p1));
            ph[nt][1] = h2u(__floats2half2_rn(p2, p3));
        }

#pragma unroll
        for (int kk = 0; kk < 4; kk++) {
            uint32_t pa[4];
            pa[0] = ph[2 * kk][0];
            pa[1] = ph[2 * kk][1];
            pa[2] = ph[2 * kk + 1][0];
            pa[3] = ph[2 * kk + 1][1];
#pragma unroll
            for (int ntp = 0; ntp < 4; ntp++) {
                uint32_t bm[4];
                ldsm4t(bm, vBase + (uint32_t)(kk * 16 * KSTRH + ntp * 16) * 2);
                mma_f16(oacc[2 * ntp], pa, bm[0], bm[1]);
                mma_f16(oacc[2 * ntp + 1], pa, bm[2], bm[3]);
            }
        }
    }

    l0 += __shfl_xor_sync(0xffffffffu, l0, 1);
    l0 += __shfl_xor_sync(0xffffffffu, l0, 2);
    l1 += __shfl_xor_sync(0xffffffffu, l1, 1);
    l1 += __shfl_xor_sync(0xffffffffu, l1, 2);
    const float inv0 = 1.f / l0;
    const float inv1 = 1.f / l1;

    __half* Ob = O + (size_t)b * SEQ * DM + h * HD;
#pragma unroll
    for (int nt = 0; nt < 8; nt++) {
        const int col = nt * 8 + 2 * tk;
        *(uint32_t*)(Ob + (size_t)r0 * DM + col) =
            h2u(__floats2half2_rn(oacc[nt][0] * inv0, oacc[nt][1] * inv0));
        *(uint32_t*)(Ob + (size_t)r1 * DM + col) =
            h2u(__floats2half2_rn(oacc[nt][2] * inv1, oacc[nt][3] * inv1));
    }
}

// ---------------------------------------------------------------------------
// kernel_launch
// ---------------------------------------------------------------------------
extern "C" void kernel_launch(void* const* d_in, const int* in_sizes, int n_in,
                              void* d_out, int out_size)
{
    const float* xq = (const float*)d_in[0];
    const float* xk = (const float*)d_in[1];
    const float* xv = (const float*)d_in[2];
    const float* Wq = (const float*)d_in[3];
    const float* bq = (const float*)d_in[4];
    const float* Wk = (const float*)d_in[5];
    const float* bk = (const float*)d_in[6];
    const float* Wv = (const float*)d_in[7];
    const float* bv = (const float*)d_in[8];
    const float* Wo = (const float*)d_in[9];
    const float* bo = (const float*)d_in[10];
    float* out = (float*)d_out;

    __half *Qh, *Kh, *Vh, *Ch, *Xq, *Xk, *Xv, *Wt;
    cudaGetSymbolAddress((void**)&Qh, g_Qh);
    cudaGetSymbolAddress((void**)&Kh, g_Kh);
    cudaGetSymbolAddress((void**)&Vh, g_Vh);
    cudaGetSymbolAddress((void**)&Ch, g_Ch);
    cudaGetSymbolAddress((void**)&Xq, g_Xq);
    cudaGetSymbolAddress((void**)&Xk, g_Xk);
    cudaGetSymbolAddress((void**)&Xv, g_Xv);
    cudaGetSymbolAddress((void**)&Wt, g_Wt);

    cudaFuncSetAttribute(gemm_qkv, cudaFuncAttributeMaxDynamicSharedMemorySize,
                         GSMEMH);
    cudaFuncSetAttribute(gemm_out, cudaFuncAttributeMaxDynamicSharedMemorySize,
                         GSMEMH);
    cudaFuncSetAttribute(attn_h, cudaFuncAttributeMaxDynamicSharedMemorySize,
                         ATTNH_SMEM);

    const int cblk = MR * DM / 8 / 256;     // 4096

    // pre-pass
    conv_h3<<<dim3(cblk, 3), 256>>>(xq, xk, xv, Xq, Xk, Xv);
    wtrans4<<<dim3(32, 32, 4), dim3(32, 8)>>>(Wq, Wk, Wv, Wo, Wt);

    // Q/K/V projections in one batched launch
    gemm_qkv<<<dim3(DM / 128, MR / 128, 3), 256, GSMEMH>>>(
        Xq, Xk, Xv, Wt, bq, bk, bv, Qh, Kh, Vh);

    // causal attention
    attn_h<<<dim3(SEQ / 128, BATCH * NH), 256, ATTNH_SMEM>>>(Qh, Kh, Vh, Ch);

    // output projection (fp32 out)
    gemm_out<<<dim3(DM / 128, MR / 128), 256, GSMEMH>>>(
        Ch, Wt + 3 * (size_t)DM * DM, bo, out);
}

// round 17
// speedup vs baseline: 8.9742x; 1.0233x over previous
#include <cuda_runtime.h>
#include <cuda_fp16.h>
#include <cstdint>

#define DM 1024
#define NH 16
#define HD 64
#define BATCH 4
#define SEQ 2048
#define MR (BATCH*SEQ)

// ---------------------------------------------------------------------------
// Scratch (static device globals -- no allocation allowed)
// ---------------------------------------------------------------------------
__device__ __half g_Qh[MR * DM];      // Q projection (half)
__device__ __half g_Kh[MR * DM];      // K projection
__device__ __half g_Vh[MR * DM];      // V projection
__device__ __half g_Ch[MR * DM];      // attention context
__device__ __half g_Xq[MR * DM];      // half-converted inputs
__device__ __half g_Xk[MR * DM];
__device__ __half g_Xv[MR * DM];
__device__ __half g_Wt[4][DM * DM];   // transposed half weights Wt[n][k] = W[k][n]

// ---------------------------------------------------------------------------
// Helpers
// ---------------------------------------------------------------------------
__device__ __forceinline__ uint32_t smem_u32(const void* p) {
    uint32_t a;
    asm("{ .reg .u64 t; cvta.to.shared.u64 t, %1; cvt.u32.u64 %0, t; }"
        : "=r"(a) : "l"(p));
    return a;
}
__device__ __forceinline__ void cp16(uint32_t dst, const void* src) {
    asm volatile("cp.async.cg.shared.global [%0], [%1], 16;" :: "r"(dst), "l"(src));
}
__device__ __forceinline__ void cp_commit() {
    asm volatile("cp.async.commit_group;" ::: "memory");
}
template <int N>
__device__ __forceinline__ void cp_wait() {
    asm volatile("cp.async.wait_group %0;" :: "n"(N) : "memory");
}
__device__ __forceinline__ float ex2(float x) {
    float y;
    asm("ex2.approx.ftz.f32 %0, %1;" : "=f"(y) : "f"(x));
    return y;
}
__device__ __forceinline__ void mma_f16(float* c, const uint32_t* a,
                                        uint32_t b0, uint32_t b1) {
    asm volatile(
        "mma.sync.aligned.m16n8k16.row.col.f32.f16.f16.f32 "
        "{%0,%1,%2,%3}, {%4,%5,%6,%7}, {%8,%9}, {%0,%1,%2,%3};"
        : "+f"(c[0]), "+f"(c[1]), "+f"(c[2]), "+f"(c[3])
        : "r"(a[0]), "r"(a[1]), "r"(a[2]), "r"(a[3]), "r"(b0), "r"(b1));
}
__device__ __forceinline__ void ldsm4(uint32_t* d, uint32_t a) {
    asm volatile("ldmatrix.sync.aligned.m8n8.x4.shared.b16 {%0,%1,%2,%3}, [%4];"
                 : "=r"(d[0]), "=r"(d[1]), "=r"(d[2]), "=r"(d[3]) : "r"(a));
}
__device__ __forceinline__ void ldsm4t(uint32_t* d, uint32_t a) {
    asm volatile("ldmatrix.sync.aligned.m8n8.x4.trans.shared.b16 {%0,%1,%2,%3}, [%4];"
                 : "=r"(d[0]), "=r"(d[1]), "=r"(d[2]), "=r"(d[3]) : "r"(a));
}
__device__ __forceinline__ uint32_t h2u(__half2 v) {
    return *reinterpret_cast<uint32_t*>(&v);
}

// ---------------------------------------------------------------------------
// fp32 -> fp16 conversion, 3 tensors in one launch (blockIdx.y selects)
// ---------------------------------------------------------------------------
__global__ __launch_bounds__(256)
void conv_h3(const float* __restrict__ i0, const float* __restrict__ i1,
             const float* __restrict__ i2, __half* __restrict__ o0,
             __half* __restrict__ o1, __half* __restrict__ o2) {
    const float* in = (blockIdx.y == 0) ? i0 : (blockIdx.y == 1) ? i1 : i2;
    __half* out = (blockIdx.y == 0) ? o0 : (blockIdx.y == 1) ? o1 : o2;
    const int i = (blockIdx.x * 256 + threadIdx.x) * 8;
    const float4 a = *(const float4*)(in + i);
    const float4 b = *(const float4*)(in + i + 4);
    uint4 u = make_uint4(h2u(__floats2half2_rn(a.x, a.y)),
                         h2u(__floats2half2_rn(a.z, a.w)),
                         h2u(__floats2half2_rn(b.x, b.y)),
                         h2u(__floats2half2_rn(b.z, b.w)));
    *(uint4*)(out + i) = u;
}

// ---------------------------------------------------------------------------
// W[K,N] fp32 -> Wt[N,K] fp16 transpose, 4 weights in one launch (blockIdx.z)
// ---------------------------------------------------------------------------
__global__ __launch_bounds__(256)
void wtrans4(const float* __restrict__ w0, const float* __restrict__ w1,
             const float* __restrict__ w2, const float* __restrict__ w3,
             __half* __restrict__ Wt) {
    const float* W = (blockIdx.z == 0) ? w0 : (blockIdx.z == 1) ? w1
                   : (blockIdx.z == 2) ? w2 : w3;
    __half* out = Wt + (size_t)blockIdx.z * DM * DM;
    __shared__ float t[32][33];
    const int bx = blockIdx.x * 32, by = blockIdx.y * 32;
    const int tx = threadIdx.x, ty = threadIdx.y;
#pragma unroll
    for (int i = 0; i < 4; i++)
        t[ty + 8 * i][tx] = W[(size_t)(by + ty + 8 * i) * DM + bx + tx];
    __syncthreads();
#pragma unroll
    for (int i = 0; i < 4; i++)
        out[(size_t)(bx + ty + 8 * i) * DM + by + tx] = __float2half_rn(t[tx][ty + 8 * i]);
}

// ---------------------------------------------------------------------------
// fp16 tensor-core GEMM core: C[8192,1024] = A[M,K] @ Wt[N,K]^T + bias
// CTA 128x128x64, 256 thr, warp 64x32, ldmatrix fragments,
// 3-stage cp.async pipeline, ONE barrier per K-iteration.
// ---------------------------------------------------------------------------
#define ASTRH 72                          // halves per smem row (144B, LDSM-safe)
#define GSTG  (2 * 128 * ASTRH)           // halves per stage (A 128x64 + B 128x64)
#define GSMEMH (3 * GSTG * 2)             // 110592 bytes (3 stages)
#define GNITER (DM / 64)                  // 16

template <typename OUT>
__device__ __forceinline__
void gemm_core(const __half* __restrict__ A, const __half* __restrict__ Wt,
               const float* __restrict__ bias, OUT* __restrict__ C,
               __half* shh)
{
    const uint32_t smb = smem_u32(shh);

    const int tid = threadIdx.x;
    const int wid = tid >> 5;
    const int lane = tid & 31;
    const int tr = lane >> 2;
    const int tk = lane & 3;
    const int wm = wid >> 2;        // 0..1
    const int wn = wid & 3;         // 0..3
    const int br = blockIdx.y, bc = blockIdx.x;

    const __half* Ab = A + (size_t)br * 128 * DM;
    const __half* Wb = Wt + (size_t)bc * 128 * DM;

    // ldmatrix lane-address offsets (bytes, within a stage half)
    const uint32_t aLane = (uint32_t)((lane & 15) * ASTRH + ((lane >> 4) << 3)) * 2;
    const uint32_t bLane = (uint32_t)(((((lane >> 4) & 1) << 3) + (lane & 7)) * ASTRH
                                      + (((lane >> 3) & 1) << 3)) * 2;

    float acc[4][4][4];
#pragma unroll
    for (int mt = 0; mt < 4; mt++)
#pragma unroll
        for (int nt = 0; nt < 4; nt++)
#pragma unroll
            for (int c = 0; c < 4; c++) acc[mt][nt][c] = 0.f;

    auto load_stage = [&](int s, int k0) {
        const uint32_t aB = smb + (uint32_t)(s * GSTG) * 2;
        const uint32_t wB = aB + 128 * ASTRH * 2;
#pragma unroll
        for (int j = 0; j < 4; j++) {
            const int idx = j * 256 + tid;   // 0..1023
            const int row = idx >> 3;        // 0..127
            const int c = idx & 7;           // 8-half chunk within 64
            cp16(aB + (uint32_t)(row * ASTRH + c * 8) * 2,
                 Ab + (size_t)row * DM + k0 + c * 8);
        }
#pragma unroll
        for (int j = 0; j < 4; j++) {
            const int idx = j * 256 + tid;
            const int row = idx >> 3;
            const int c = idx & 7;
            cp16(wB + (uint32_t)(row * ASTRH + c * 8) * 2,
                 Wb + (size_t)row * DM + k0 + c * 8);
        }
        cp_commit();
    };

    // prologue: 2 stages in flight
    load_stage(0, 0);
    load_stage(1, 64);

    for (int i = 0; i < GNITER; i++) {
        if (i + 1 < GNITER) cp_wait<1>(); else cp_wait<0>();
        __syncthreads();
        // issue next load AFTER barrier: all warps finished reading stage (i-1)%3
        if (i + 2 < GNITER) load_stage((i + 2) % 3, (i + 2) * 64);

        const uint32_t asB = smb + (uint32_t)(((i % 3) * GSTG) * 2);
        const uint32_t wsB = asB + 128 * ASTRH * 2;
        const uint32_t aWarp = asB + aLane + (uint32_t)(wm * 64 * ASTRH) * 2;
        const uint32_t bWarp = wsB + bLane + (uint32_t)(wn * 32 * ASTRH) * 2;

#pragma unroll
        for (int ks = 0; ks < 4; ks++) {
            const uint32_t kb = (uint32_t)(ks * 16) * 2;
            uint32_t af[4][4], bf[2][4];
#pragma unroll
            for (int mt = 0; mt < 4; mt++)
                ldsm4(af[mt], aWarp + (uint32_t)(mt * 16 * ASTRH) * 2 + kb);
#pragma unroll
            for (int np = 0; np < 2; np++)
                ldsm4(bf[np], bWarp + (uint32_t)(np * 16 * ASTRH) * 2 + kb);
#pragma unroll
            for (int mt = 0; mt < 4; mt++) {
#pragma unroll
                for (int np = 0; np < 2; np++) {
                    mma_f16(acc[mt][2 * np], af[mt], bf[np][0], bf[np][1]);
                    mma_f16(acc[mt][2 * np + 1], af[mt], bf[np][2], bf[np][3]);
                }
            }
        }
    }

    // epilogue: bias in fp32, store fp32 or half2
#pragma unroll
    for (int mt = 0; mt < 4; mt++) {
        const int row = br * 128 + wm * 64 + mt * 16 + tr;
#pragma unroll
        for (int nt = 0; nt < 4; nt++) {
            const int col = bc * 128 + wn * 32 + nt * 8 + 2 * tk;
            const float2 bv = *(const float2*)(bias + col);
            const float v0 = acc[mt][nt][0] + bv.x;
            const float v1 = acc[mt][nt][1] + bv.y;
            const float v2 = acc[mt][nt][2] + bv.x;
            const float v3 = acc[mt][nt][3] + bv.y;
            if constexpr (sizeof(OUT) == 4) {
                *(float2*)((float*)C + (size_t)row * DM + col) = make_float2(v0, v1);
                *(float2*)((float*)C + (size_t)(row + 8) * DM + col) = make_float2(v2, v3);
            } else {
                *(uint32_t*)((__half*)C + (size_t)row * DM + col) =
                    h2u(__floats2half2_rn(v0, v1));
                *(uint32_t*)((__half*)C + (size_t)(row + 8) * DM + col) =
                    h2u(__floats2half2_rn(v2, v3));
            }
        }
    }
}

// Batched Q/K/V projection: blockIdx.z selects the GEMM
__global__ __launch_bounds__(256, 2)
void gemm_qkv(const __half* __restrict__ A0, const __half* __restrict__ A1,
              const __half* __restrict__ A2, const __half* __restrict__ Wt,
              const float* __restrict__ b0, const float* __restrict__ b1,
              const float* __restrict__ b2, __half* __restrict__ C0,
              __half* __restrict__ C1, __half* __restrict__ C2)
{
    extern __shared__ __half shh[];
    const int z = blockIdx.z;
    const __half* A = (z == 0) ? A0 : (z == 1) ? A1 : A2;
    const float* bias = (z == 0) ? b0 : (z == 1) ? b1 : b2;
    __half* C = (z == 0) ? C0 : (z == 1) ? C1 : C2;
    gemm_core<__half>(A, Wt + (size_t)z * DM * DM, bias, C, shh);
}

// Output projection (fp32 out)
__global__ __launch_bounds__(256, 2)
void gemm_out(const __half* __restrict__ A, const __half* __restrict__ Wt,
              const float* __restrict__ bias, float* __restrict__ C)
{
    extern __shared__ __half shh[];
    gemm_core<float>(A, Wt, bias, C, shh);
}

// ---------------------------------------------------------------------------
// fp16 tensor-core causal flash attention (register-P, 4-stage cp.async,
// l computed via ones-column mma -- no scalar row-sum adds, no final shfls)
// ---------------------------------------------------------------------------
#define KSTRH 72
#define AT_STG (2 * 64 * KSTRH)
#define ATTNH_SMEM (4 * AT_STG * 2)
#define ONES2 0x3C003C00u                 // half2(1.0, 1.0)

__global__ __launch_bounds__(256, 2)
void attn_h(const __half* __restrict__ Q, const __half* __restrict__ K,
            const __half* __restrict__ V, __half* __restrict__ O)
{
    extern __shared__ __half sh2[];
    const uint32_t smb = smem_u32(sh2);
    const int tid = threadIdx.x;
    const int wid = tid >> 5;
    const int lane = tid & 31;
    const int tr = lane >> 2;
    const int tk = lane & 3;
    const int qb = (SEQ / 128 - 1) - blockIdx.x;
    const int b = blockIdx.y >> 4;
    const int h = blockIdx.y & 15;

    const int r8 = lane & 7;
    const int b3 = (lane >> 3) & 1;
    const int b4 = (lane >> 4) & 1;
    const uint32_t kOff = (uint32_t)((b4 * 8 + r8) * KSTRH + b3 * 8) * 2;
    const uint32_t vOff = (uint32_t)(64 * KSTRH + (r8 + b3 * 8) * KSTRH + b4 * 8) * 2;

    const int r0 = qb * 128 + wid * 16 + tr;
    const int r1 = r0 + 8;

    const __half* Kbh = K + (size_t)b * SEQ * DM + h * HD;
    const __half* Vbh = V + (size_t)b * SEQ * DM + h * HD;
    const int ntiles = 2 * (qb + 1);

    auto load_stage = [&](int s, int kt) {
        const uint32_t base = smb + (uint32_t)(s * AT_STG) * 2;
#pragma unroll
        for (int j = 0; j < 2; j++) {
            const int idx = j * 256 + tid;
            const int key = idx >> 3;
            const int c = idx & 7;
            const size_t go = (size_t)(kt * 64 + key) * DM + c * 8;
            cp16(base + (uint32_t)(key * KSTRH + c * 8) * 2, Kbh + go);
            cp16(base + (uint32_t)((64 + key) * KSTRH + c * 8) * 2, Vbh + go);
        }
        cp_commit();
    };

    load_stage(0, 0);
    if (ntiles > 1) load_stage(1, 1);

    const float qs = 0.125f * 1.4426950408889634f;
    const __half* Qbh = Q + (size_t)b * SEQ * DM + h * HD;
    uint32_t qf[4][4];
#pragma unroll
    for (int kc = 0; kc < 4; kc++) {
        const __half* p0 = Qbh + (size_t)r0 * DM + kc * 16 + 2 * tk;
        const __half* p1 = Qbh + (size_t)r1 * DM + kc * 16 + 2 * tk;
#pragma unroll
        for (int j = 0; j < 4; j++) {
            const __half* p = (j & 1) ? p1 : p0;
            const float2 f = __half22float2(*(const __half2*)(p + (j >> 1) * 8));
            qf[kc][j] = h2u(__floats2half2_rn(f.x * qs, f.y * qs));
        }
    }

    float oacc[8][4];
#pragma unroll
    for (int nt = 0; nt < 8; nt++)
#pragma unroll
        for (int c = 0; c < 4; c++) oacc[nt][c] = 0.f;
    float lacc[4] = {0.f, 0.f, 0.f, 0.f};     // l via P @ ones (cols 0/2 used)
    float m0 = -1e30f, m1 = -1e30f;

    for (int kt = 0; kt < ntiles; kt++) {
        if (kt + 2 < ntiles) {
            load_stage((kt + 2) & 3, kt + 2);
            cp_wait<2>();
        } else if (kt + 1 < ntiles) {
            cp_wait<1>();
        } else {
            cp_wait<0>();
        }
        __syncthreads();

        const uint32_t stg = smb + (uint32_t)(((kt & 3) * AT_STG) * 2);
        const uint32_t kBase = stg + kOff;
        const uint32_t vBase = stg + vOff;

        float sacc[8][4];
#pragma unroll
        for (int nt = 0; nt < 8; nt++)
#pragma unroll
            for (int c = 0; c < 4; c++) sacc[nt][c] = 0.f;

#pragma unroll
        for (int kc = 0; kc < 4; kc++) {
#pragma unroll
            for (int ntp = 0; ntp < 4; ntp++) {
                uint32_t bm[4];
                ldsm4(bm, kBase + (uint32_t)(ntp * 16 * KSTRH + kc * 16) * 2);
                mma_f16(sacc[2 * ntp], qf[kc], bm[0], bm[1]);
                mma_f16(sacc[2 * ntp + 1], qf[kc], bm[2], bm[3]);
            }
        }

        if (kt >= 2 * qb) {
#pragma unroll
            for (int nt = 0; nt < 8; nt++) {
                const int c0 = kt * 64 + nt * 8 + 2 * tk;
                if (c0 > r0)     sacc[nt][0] = -1e30f;
                if (c0 + 1 > r0) sacc[nt][1] = -1e30f;
                if (c0 > r1)     sacc[nt][2] = -1e30f;
                if (c0 + 1 > r1) sacc[nt][3] = -1e30f;
            }
        }

        float mn0 = m0, mn1 = m1;
#pragma unroll
        for (int nt = 0; nt < 8; nt++) {
            mn0 = fmaxf(mn0, fmaxf(sacc[nt][0], sacc[nt][1]));
            mn1 = fmaxf(mn1, fmaxf(sacc[nt][2], sacc[nt][3]));
        }
        mn0 = fmaxf(mn0, __shfl_xor_sync(0xffffffffu, mn0, 1));
        mn0 = fmaxf(mn0, __shfl_xor_sync(0xffffffffu, mn0, 2));
        mn1 = fmaxf(mn1, __shfl_xor_sync(0xffffffffu, mn1, 1));
        mn1 = fmaxf(mn1, __shfl_xor_sync(0xffffffffu, mn1, 2));

        const float cr0 = ex2(m0 - mn0);
        const float cr1 = ex2(m1 - mn1);
        m0 = mn0; m1 = mn1;
        lacc[0] *= cr0; lacc[1] *= cr0;
        lacc[2] *= cr1; lacc[3] *= cr1;
#pragma unroll
        for (int nt = 0; nt < 8; nt++) {
            oacc[nt][0] *= cr0; oacc[nt][1] *= cr0;
            oacc[nt][2] *= cr1; oacc[nt][3] *= cr1;
        }

        uint32_t ph[8][2];
#pragma unroll
        for (int nt = 0; nt < 8; nt++) {
            const float p0 = ex2(sacc[nt][0] - m0);
            const float p1 = ex2(sacc[nt][1] - m0);
            const float p2 = ex2(sacc[nt][2] - m1);
            const float p3 = ex2(sacc[nt][3] - m1);
            ph[nt][0] = h2u(__floats2half2_rn(p0, p1));
            ph[nt][1] = h2u(__floats2half2_rn(p2, p3));
        }

#pragma unroll
        for (int kk = 0; kk < 4; kk++) {
            uint32_t pa[4];
            pa[0] = ph[2 * kk][0];
            pa[1] = ph[2 * kk][1];
            pa[2] = ph[2 * kk + 1][0];
            pa[3] = ph[2 * kk + 1][1];
            // row-sum of P into lacc (B = all ones, no ldsm needed)
            mma_f16(lacc, pa, ONES2, ONES2);
#pragma unroll
            for (int ntp = 0; ntp < 4; ntp++) {
                uint32_t bm[4];
                ldsm4t(bm, vBase + (uint32_t)(kk * 16 * KSTRH + ntp * 16) * 2);
                mma_f16(oacc[2 * ntp], pa, bm[0], bm[1]);
                mma_f16(oacc[2 * ntp + 1], pa, bm[2], bm[3]);
            }
        }
    }

    const float inv0 = 1.f / lacc[0];
    const float inv1 = 1.f / lacc[2];

    __half* Ob = O + (size_t)b * SEQ * DM + h * HD;
#pragma unroll
    for (int nt = 0; nt < 8; nt++) {
        const int col = nt * 8 + 2 * tk;
        *(uint32_t*)(Ob + (size_t)r0 * DM + col) =
            h2u(__floats2half2_rn(oacc[nt][0] * inv0, oacc[nt][1] * inv0));
        *(uint32_t*)(Ob + (size_t)r1 * DM + col) =
            h2u(__floats2half2_rn(oacc[nt][2] * inv1, oacc[nt][3] * inv1));
    }
}

// ---------------------------------------------------------------------------
// kernel_launch
// ---------------------------------------------------------------------------
extern "C" void kernel_launch(void* const* d_in, const int* in_sizes, int n_in,
                              void* d_out, int out_size)
{
    const float* xq = (const float*)d_in[0];
    const float* xk = (const float*)d_in[1];
    const float* xv = (const float*)d_in[2];
    const float* Wq = (const float*)d_in[3];
    const float* bq = (const float*)d_in[4];
    const float* Wk = (const float*)d_in[5];
    const float* bk = (const float*)d_in[6];
    const float* Wv = (const float*)d_in[7];
    const float* bv = (const float*)d_in[8];
    const float* Wo = (const float*)d_in[9];
    const float* bo = (const float*)d_in[10];
    float* out = (float*)d_out;

    __half *Qh, *Kh, *Vh, *Ch, *Xq, *Xk, *Xv, *Wt;
    cudaGetSymbolAddress((void**)&Qh, g_Qh);
    cudaGetSymbolAddress((void**)&Kh, g_Kh);
    cudaGetSymbolAddress((void**)&Vh, g_Vh);
    cudaGetSymbolAddress((void**)&Ch, g_Ch);
    cudaGetSymbolAddress((void**)&Xq, g_Xq);
    cudaGetSymbolAddress((void**)&Xk, g_Xk);
    cudaGetSymbolAddress((void**)&Xv, g_Xv);
    cudaGetSymbolAddress((void**)&Wt, g_Wt);

    cudaFuncSetAttribute(gemm_qkv, cudaFuncAttributeMaxDynamicSharedMemorySize,
                         GSMEMH);
    cudaFuncSetAttribute(gemm_out, cudaFuncAttributeMaxDynamicSharedMemorySize,
                         GSMEMH);
    cudaFuncSetAttribute(attn_h, cudaFuncAttributeMaxDynamicSharedMemorySize,
                         ATTNH_SMEM);

    const int cblk = MR * DM / 8 / 256;     // 4096

    // pre-pass
    conv_h3<<<dim3(cblk, 3), 256>>>(xq, xk, xv, Xq, Xk, Xv);
    wtrans4<<<dim3(32, 32, 4), dim3(32, 8)>>>(Wq, Wk, Wv, Wo, Wt);

    // Q/K/V projections in one batched launch
    gemm_qkv<<<dim3(DM / 128, MR / 128, 3), 256, GSMEMH>>>(
        Xq, Xk, Xv, Wt, bq, bk, bv, Qh, Kh, Vh);

    // causal attention
    attn_h<<<dim3(SEQ / 128, BATCH * NH), 256, ATTNH_SMEM>>>(Qh, Kh, Vh, Ch);

    // output projection (fp32 out)
    gemm_out<<<dim3(DM / 128, MR / 128), 256, GSMEMH>>>(
        Ch, Wt + 3 * (size_t)DM * DM, bo, out);
}